// round 13
// baseline (speedup 1.0000x reference)
#include <cuda_runtime.h>
#include <cuda_fp16.h>

#define D 64
#define NB 1024
#define XS 68   // float smem row stride (272B, 16B-aligned)

#define NS_ROWS 50001   // E_s rows
#define ND_ROWS 2001    // E_d rows

// Scratch (allocation-free rule: __device__ globals)
// Weight layout: g_Wt2[m*4096 + (e>>1)*128 + d*2 + (e&1)] = W[m][d][e]
// -> 4 halves at (ep, d even): {W(2ep,d), W(2ep+1,d), W(2ep,d+1), W(2ep+1,d+1)}
__device__ __align__(16) __half g_Wt2[8 * D * D];
__device__ __align__(16) __half g_Es2[NS_ROWS * D];  // fp16 E_s
__device__ __align__(16) __half g_Ed2[ND_ROWS * D];  // fp16 E_d
__device__ __align__(16) float g_UA[NB * 8 * D];     // u1 + S
__device__ __align__(16) float g_UB[NB * 8 * D];     // S * u1
__device__ __align__(16) float g_dise[NB * D];       // emb_dise
__device__ int g_cnt[NB];                            // completion counters

typedef unsigned long long ull;

__device__ __forceinline__ float leaky(float x) { return fmaxf(x, 0.2f * x); }
__device__ __forceinline__ float avgw(int cnt)  { return cnt > 0 ? 1.0f / ((float)cnt + 1e-8f) : 0.0f; }

__device__ __forceinline__ ull pack2(float x, float y) {
    ull r; asm("mov.b64 %0, {%1, %2};" : "=l"(r) : "f"(x), "f"(y)); return r;
}
__device__ __forceinline__ float2 unpack2(ull v) {
    float2 f; asm("mov.b64 {%0, %1}, %2;" : "=f"(f.x), "=f"(f.y) : "l"(v)); return f;
}
__device__ __forceinline__ void fma2(ull& acc, ull a, ull b) {
    asm("fma.rn.f32x2 %0, %1, %2, %3;" : "=l"(acc) : "l"(a), "l"(b), "l"(acc));
}

// load 4 halves (8B) and widen to float4
__device__ __forceinline__ float4 ldh4(const __half* p) {
    uint2 raw = *(const uint2*)p;
    __half2 h0 = *reinterpret_cast<__half2*>(&raw.x);
    __half2 h1 = *reinterpret_cast<__half2*>(&raw.y);
    float2 a = __half22float2(h0), b = __half22float2(h1);
    return make_float4(a.x, a.y, b.x, b.y);
}

// load 4 fp16 weights (8B, one LDG.64) for (e-pair, dims d:d+1);
// returns {.x = {W(e,d),W(e+1,d)}, .y = {W(e,d+1),W(e+1,d+1)}} widened to f32 pairs
__device__ __forceinline__ ulonglong2 ldw4(const __half* p) {
    uint2 raw = *(const uint2*)p;
    __half2 h0 = *reinterpret_cast<__half2*>(&raw.x);
    __half2 h1 = *reinterpret_cast<__half2*>(&raw.y);
    float2 f0 = __half22float2(h0);
    float2 f1 = __half22float2(h1);
    ulonglong2 r;
    r.x = pack2(f0.x, f0.y);
    r.y = pack2(f1.x, f1.y);
    return r;
}

// ---------------------------------------------------------------------------
// K0: prep — fp16 conversion of E_s/E_d, fp16 weight re-layout, counters
// ---------------------------------------------------------------------------
#define CV_S ((NS_ROWS * D / 4 + 255) / 256)   // 3126
#define CV_D ((ND_ROWS * D / 4 + 255) / 256)   // 126
#define TP_B 64
#define CN_B 4
#define PREP_GRID (CV_S + CV_D + TP_B + CN_B)

__global__ void __launch_bounds__(256)
k_prep(const float* __restrict__ E_s, const float* __restrict__ E_d,
       const float* __restrict__ w0, const float* __restrict__ w1,
       const float* __restrict__ w2, const float* __restrict__ w3,
       const float* __restrict__ w4, const float* __restrict__ w5,
       const float* __restrict__ w6, const float* __restrict__ w7) {
    int bid = blockIdx.x, t = threadIdx.x;
    if (bid < CV_S) {
        int i = bid * 256 + t;
        if (i < NS_ROWS * D / 4) {
            float4 v = *(const float4*)(E_s + i * 4);
            __half2 h0 = __floats2half2_rn(v.x, v.y);
            __half2 h1 = __floats2half2_rn(v.z, v.w);
            uint2 u;
            u.x = *reinterpret_cast<unsigned*>(&h0);
            u.y = *reinterpret_cast<unsigned*>(&h1);
            *(uint2*)(g_Es2 + i * 4) = u;
        }
    } else if (bid < CV_S + CV_D) {
        int i = (bid - CV_S) * 256 + t;
        if (i < ND_ROWS * D / 4) {
            float4 v = *(const float4*)(E_d + i * 4);
            __half2 h0 = __floats2half2_rn(v.x, v.y);
            __half2 h1 = __floats2half2_rn(v.z, v.w);
            uint2 u;
            u.x = *reinterpret_cast<unsigned*>(&h0);
            u.y = *reinterpret_cast<unsigned*>(&h1);
            *(uint2*)(g_Ed2 + i * 4) = u;
        }
    } else if (bid < CV_S + CV_D + TP_B) {
        const float* Ws[8] = {w0, w1, w2, w3, w4, w5, w6, w7};
        int k = (bid - CV_S - CV_D) * 256 + t;   // [0, 16384)
#pragma unroll
        for (int p = 0; p < 2; ++p) {
            int idx = k + p * 16384;             // linear: m,d,e
            int m = idx >> 12, de = idx & 4095;
            int d = de >> 6, e = de & 63;
            g_Wt2[m * 4096 + (e >> 1) * 128 + d * 2 + (e & 1)] =
                __float2half_rn(Ws[m][d * D + e]);
        }
    } else {
        int i = (bid - CV_S - CV_D - TP_B) * 256 + t;
        g_cnt[i] = 0;
    }
}

// ---------------------------------------------------------------------------
// K1: blocks [0, NB): dsd per b.  blocks [NB, 9*NB): usu inner per (b,g).
// 128 threads. Matvec: 4 warp-chunks (16 e) x 32 lanes (dims 2l, 2l+1);
// e-parity-pair accumulation: x operand is natural {x_e,x_e+1} (no dup movs),
// weights pre-interleaved for one LDG.64 per (e-pair, 2 dims).
// 9th finisher per b runs finalization in place.
// ---------------------------------------------------------------------------
__global__ void __launch_bounds__(128, 6)
k_inner(const int* __restrict__ label,
        const int* __restrict__ dsd_1, const int* __restrict__ dsd_2,
        const int* __restrict__ usu_1, const int* __restrict__ usu_2,
        const int* __restrict__ usu_3, float* __restrict__ out) {
    int t = threadIdx.x;
    int g16 = t >> 4, lane = t & 15, d4 = lane * 4;
    int c4 = t >> 5, l31 = t & 31, d2 = l31 * 2;
    int woff = l31 * 4;   // half-offset of this lane's dim-pair within an e-pair row

    __shared__ __align__(16) float shX[8 * XS];
    __shared__ __align__(16) float shY[8 * XS];
    __shared__ float shP[4][8][D];
    __shared__ float shL[4][XS];
    __shared__ int sFin;

    int b;

    if (blockIdx.x >= NB) {
        // ===================== usu inner: one (b,g) per block ================
        int bg = blockIdx.x - NB;
        b = bg >> 3;

        float4 u = make_float4(0.f, 0.f, 0.f, 0.f);
        int c2 = 0;
        if (t < 16) {
            int iu = __ldg(usu_1 + bg);
            u = ldh4(g_Es2 + iu * D + t * 4);
            int4 m0 = __ldg((const int4*)(usu_2 + bg * 8));
            int4 m1 = __ldg((const int4*)(usu_2 + bg * 8 + 4));
            c2 = (m0.x != 0) + (m0.y != 0) + (m0.z != 0) + (m0.w != 0)
               + (m1.x != 0) + (m1.y != 0) + (m1.z != 0) + (m1.w != 0);
        }

        const int4* ip = (const int4*)(usu_3 + (bg * 8 + g16) * 16);
        int4 i0 = __ldg(ip), i1 = __ldg(ip + 1), i2 = __ldg(ip + 2), i3 = __ldg(ip + 3);
        int cnt = (i0.x != 0) + (i0.y != 0) + (i0.z != 0) + (i0.w != 0)
                + (i1.x != 0) + (i1.y != 0) + (i1.z != 0) + (i1.w != 0)
                + (i2.x != 0) + (i2.y != 0) + (i2.z != 0) + (i2.w != 0)
                + (i3.x != 0) + (i3.y != 0) + (i3.z != 0) + (i3.w != 0);

        float sx = 0.f, sy = 0.f, sz = 0.f, sw = 0.f;
#define ACC(ix) { float4 v = ldh4(g_Es2 + (ix) * D + d4); \
                  sx += v.x; sy += v.y; sz += v.z; sw += v.w; }
        ACC(i0.x) ACC(i0.y) ACC(i0.z) ACC(i0.w)
        ACC(i1.x) ACC(i1.y) ACC(i1.z) ACC(i1.w)
        ACC(i2.x) ACC(i2.y) ACC(i2.z) ACC(i2.w)
        ACC(i3.x) ACC(i3.y) ACC(i3.z) ACC(i3.w)
#undef ACC
        float w = avgw(cnt);
        *(float4*)&shX[g16 * XS + d4] = make_float4(sx * w, sy * w, sz * w, sw * w);
        __syncthreads();

        // matvec W3: e-chunk c4*16, dims (2*l31, 2*l31+1), 8 rows
        {
            const __half* W3t = g_Wt2 + 4 * 4096;
            ull accA[8], accB[8];
#pragma unroll
            for (int j = 0; j < 8; ++j) { accA[j] = 0ull; accB[j] = 0ull; }
#pragma unroll
            for (int q = 0; q < 4; ++q) {
                int e = c4 * 16 + q * 4;
                int ep = e >> 1;
                ulonglong2 w0 = ldw4(W3t + ep * 128 + woff);
                ulonglong2 w1 = ldw4(W3t + (ep + 1) * 128 + woff);
#pragma unroll
                for (int j = 0; j < 8; ++j) {
                    ulonglong2 xx = *(const ulonglong2*)&shX[j * XS + e];
                    fma2(accA[j], xx.x, w0.x);
                    fma2(accB[j], xx.x, w0.y);
                    fma2(accA[j], xx.y, w1.x);
                    fma2(accB[j], xx.y, w1.y);
                }
            }
#pragma unroll
            for (int j = 0; j < 8; ++j) {
                float2 a = unpack2(accA[j]), bb = unpack2(accB[j]);
                *(float2*)&shP[c4][j][d2] = make_float2(a.x + a.y, bb.x + bb.y);
            }
        }
        __syncthreads();

        // reduce 4 chunks + leaky + pairwise j via shfl
        {
            float rx = 0.f, ry = 0.f, rz = 0.f, rw = 0.f;
#pragma unroll
            for (int c = 0; c < 4; ++c) {
                float4 p = *(float4*)&shP[c][g16][d4];
                rx += p.x; ry += p.y; rz += p.z; rw += p.w;
            }
            rx = leaky(rx); ry = leaky(ry); rz = leaky(rz); rw = leaky(rw);
            rx += __shfl_down_sync(0xffffffffu, rx, 16);
            ry += __shfl_down_sync(0xffffffffu, ry, 16);
            rz += __shfl_down_sync(0xffffffffu, rz, 16);
            rw += __shfl_down_sync(0xffffffffu, rw, 16);
            if ((t & 16) == 0)
                *(float4*)&shL[t >> 5][d4] = make_float4(rx, ry, rz, rw);
        }
        __syncthreads();

        if (t < 16) {
            int dd = t * 4;
            float Sx = 0.f, Sy = 0.f, Sz = 0.f, Sw = 0.f;
#pragma unroll
            for (int wi = 0; wi < 4; ++wi) {
                float4 l = *(float4*)&shL[wi][dd];
                Sx += l.x; Sy += l.y; Sz += l.z; Sw += l.w;
            }
            float w2 = avgw(c2);
            Sx *= w2; Sy *= w2; Sz *= w2; Sw *= w2;
            *(float4*)&g_UA[bg * D + dd] = make_float4(u.x + Sx, u.y + Sy, u.z + Sz, u.w + Sw);
            *(float4*)&g_UB[bg * D + dd] = make_float4(Sx * u.x, Sy * u.y, Sz * u.z, Sw * u.w);
            __threadfence();
        }
        __syncthreads();
    } else {
        // ===================== dsd full path: one b per block ================
        b = blockIdx.x;

        float4 td4 = make_float4(0.f, 0.f, 0.f, 0.f);
        int c1 = 0;
        if (t < 16) {
            int lb = __ldg(label + b);
            td4 = ldh4(g_Ed2 + lb * D + t * 4);
            int4 m0 = __ldg((const int4*)(dsd_1 + b * 8));
            int4 m1 = __ldg((const int4*)(dsd_1 + b * 8 + 4));
            c1 = (m0.x != 0) + (m0.y != 0) + (m0.z != 0) + (m0.w != 0)
               + (m1.x != 0) + (m1.y != 0) + (m1.z != 0) + (m1.w != 0);
        }

        int ies = __ldg(dsd_1 + b * 8 + g16);
        const int4* ip = (const int4*)(dsd_2 + (b * 8 + g16) * 8);
        int4 i0 = __ldg(ip), i1 = __ldg(ip + 1);
        int cnt = (i0.x != 0) + (i0.y != 0) + (i0.z != 0) + (i0.w != 0)
                + (i1.x != 0) + (i1.y != 0) + (i1.z != 0) + (i1.w != 0);

        float4 es = ldh4(g_Es2 + ies * D + d4);
        float sx = 0.f, sy = 0.f, sz = 0.f, sw = 0.f;
#define ACC(ix) { float4 v = ldh4(g_Ed2 + (ix) * D + d4); \
                  sx += v.x; sy += v.y; sz += v.z; sw += v.w; }
        ACC(i0.x) ACC(i0.y) ACC(i0.z) ACC(i0.w)
        ACC(i1.x) ACC(i1.y) ACC(i1.z) ACC(i1.w)
#undef ACC
        float w = avgw(cnt);
        float ax = sx * w, ay = sy * w, az = sz * w, aw = sw * w;
        *(float4*)&shX[g16 * XS + d4] = make_float4(es.x + ax, es.y + ay, es.z + az, es.w + aw);
        *(float4*)&shY[g16 * XS + d4] = make_float4(ax * es.x, ay * es.y, az * es.z, aw * es.w);
        __syncthreads();

        // hop1 dual matvec W21/W22
        {
            const __half* W21t = g_Wt2 + 0 * 4096;
            const __half* W22t = g_Wt2 + 1 * 4096;
            ull accA[8], accB[8];
#pragma unroll
            for (int j = 0; j < 8; ++j) { accA[j] = 0ull; accB[j] = 0ull; }
#pragma unroll
            for (int q = 0; q < 4; ++q) {
                int e = c4 * 16 + q * 4;
                int ep = e >> 1;
                ulonglong2 wa0 = ldw4(W21t + ep * 128 + woff);
                ulonglong2 wa1 = ldw4(W21t + (ep + 1) * 128 + woff);
                ulonglong2 wb0 = ldw4(W22t + ep * 128 + woff);
                ulonglong2 wb1 = ldw4(W22t + (ep + 1) * 128 + woff);
#pragma unroll
                for (int j = 0; j < 8; ++j) {
                    ulonglong2 xx = *(const ulonglong2*)&shX[j * XS + e];
                    ulonglong2 yy = *(const ulonglong2*)&shY[j * XS + e];
                    fma2(accA[j], xx.x, wa0.x);
                    fma2(accB[j], xx.x, wa0.y);
                    fma2(accA[j], xx.y, wa1.x);
                    fma2(accB[j], xx.y, wa1.y);
                    fma2(accA[j], yy.x, wb0.x);
                    fma2(accB[j], yy.x, wb0.y);
                    fma2(accA[j], yy.y, wb1.x);
                    fma2(accB[j], yy.y, wb1.y);
                }
            }
#pragma unroll
            for (int j = 0; j < 8; ++j) {
                float2 a = unpack2(accA[j]), bb = unpack2(accB[j]);
                *(float2*)&shP[c4][j][d2] = make_float2(a.x + a.y, bb.x + bb.y);
            }
        }
        __syncthreads();

        // reduce + leaky + pairwise shfl
        {
            float rx = 0.f, ry = 0.f, rz = 0.f, rw = 0.f;
#pragma unroll
            for (int c = 0; c < 4; ++c) {
                float4 p = *(float4*)&shP[c][g16][d4];
                rx += p.x; ry += p.y; rz += p.z; rw += p.w;
            }
            rx = leaky(rx); ry = leaky(ry); rz = leaky(rz); rw = leaky(rw);
            rx += __shfl_down_sync(0xffffffffu, rx, 16);
            ry += __shfl_down_sync(0xffffffffu, ry, 16);
            rz += __shfl_down_sync(0xffffffffu, rz, 16);
            rw += __shfl_down_sync(0xffffffffu, rw, 16);
            if ((t & 16) == 0)
                *(float4*)&shL[t >> 5][d4] = make_float4(rx, ry, rz, rw);
        }
        __syncthreads();

        // hop2 inputs
        if (t < 16) {
            int dd = t * 4;
            float Ax = 0.f, Ay = 0.f, Az = 0.f, Aw = 0.f;
#pragma unroll
            for (int wi = 0; wi < 4; ++wi) {
                float4 l = *(float4*)&shL[wi][dd];
                Ax += l.x; Ay += l.y; Az += l.z; Aw += l.w;
            }
            float w1 = avgw(c1);
            Ax *= w1; Ay *= w1; Az *= w1; Aw *= w1;
            *(float4*)&shX[dd] = make_float4(Ax + td4.x, Ay + td4.y, Az + td4.z, Aw + td4.w);
            *(float4*)&shY[dd] = make_float4(Ax * td4.x, Ay * td4.y, Az * td4.z, Aw * td4.w);
        }
        __syncthreads();

        // hop2 dual matvec W11/W12 (1 row)
        {
            const __half* W11t = g_Wt2 + 2 * 4096;
            const __half* W12t = g_Wt2 + 3 * 4096;
            ull accA = 0ull, accB = 0ull;
#pragma unroll
            for (int q = 0; q < 4; ++q) {
                int e = c4 * 16 + q * 4;
                int ep = e >> 1;
                ulonglong2 wa0 = ldw4(W11t + ep * 128 + woff);
                ulonglong2 wa1 = ldw4(W11t + (ep + 1) * 128 + woff);
                ulonglong2 wb0 = ldw4(W12t + ep * 128 + woff);
                ulonglong2 wb1 = ldw4(W12t + (ep + 1) * 128 + woff);
                ulonglong2 xx = *(const ulonglong2*)&shX[e];
                ulonglong2 yy = *(const ulonglong2*)&shY[e];
                fma2(accA, xx.x, wa0.x);
                fma2(accB, xx.x, wa0.y);
                fma2(accA, xx.y, wa1.x);
                fma2(accB, xx.y, wa1.y);
                fma2(accA, yy.x, wb0.x);
                fma2(accB, yy.x, wb0.y);
                fma2(accA, yy.y, wb1.x);
                fma2(accB, yy.y, wb1.y);
            }
            float2 a = unpack2(accA), bb = unpack2(accB);
            *(float2*)&shP[c4][0][d2] = make_float2(a.x + a.y, bb.x + bb.y);
        }
        __syncthreads();

        if (t < 16) {
            int dd = t * 4;
            float rx = 0.f, ry = 0.f, rz = 0.f, rw = 0.f;
#pragma unroll
            for (int c = 0; c < 4; ++c) {
                float4 p = *(float4*)&shP[c][0][dd];
                rx += p.x; ry += p.y; rz += p.z; rw += p.w;
            }
            *(float4*)&g_dise[b * D + dd] =
                make_float4(leaky(rx), leaky(ry), leaky(rz), leaky(rw));
            __threadfence();
        }
        __syncthreads();
    }

    // ======================= completion + finalization =======================
    if (t == 0) {
        int old = atomicAdd(&g_cnt[b], 1);
        if (old == 8) { __threadfence(); sFin = 1; } else sFin = 0;
    }
    __syncthreads();
    if (!sFin) return;

    // --- finalization: es1 matvec + i-avg + W1u matvec + dot with dise ---
    float4 dz = make_float4(0.f, 0.f, 0.f, 0.f);
    int c1u = 0;
    if (t < 16) {
        dz = *(const float4*)&g_dise[b * D + t * 4];
        int4 m0 = __ldg((const int4*)(usu_1 + b * 8));
        int4 m1 = __ldg((const int4*)(usu_1 + b * 8 + 4));
        c1u = (m0.x != 0) + (m0.y != 0) + (m0.z != 0) + (m0.w != 0)
            + (m1.x != 0) + (m1.y != 0) + (m1.z != 0) + (m1.w != 0);
    }
    *(float4*)&shX[g16 * XS + d4] = *(const float4*)&g_UA[(b * 8 + g16) * D + d4];
    *(float4*)&shY[g16 * XS + d4] = *(const float4*)&g_UB[(b * 8 + g16) * D + d4];
    __syncthreads();

    // es1 dual matvec W21u/W22u
    {
        const __half* W21t = g_Wt2 + 5 * 4096;
        const __half* W22t = g_Wt2 + 6 * 4096;
        ull accA[8], accB[8];
#pragma unroll
        for (int j = 0; j < 8; ++j) { accA[j] = 0ull; accB[j] = 0ull; }
#pragma unroll
        for (int q = 0; q < 4; ++q) {
            int e = c4 * 16 + q * 4;
            int ep = e >> 1;
            ulonglong2 wa0 = ldw4(W21t + ep * 128 + woff);
            ulonglong2 wa1 = ldw4(W21t + (ep + 1) * 128 + woff);
            ulonglong2 wb0 = ldw4(W22t + ep * 128 + woff);
            ulonglong2 wb1 = ldw4(W22t + (ep + 1) * 128 + woff);
#pragma unroll
            for (int j = 0; j < 8; ++j) {
                ulonglong2 xx = *(const ulonglong2*)&shX[j * XS + e];
                ulonglong2 yy = *(const ulonglong2*)&shY[j * XS + e];
                fma2(accA[j], xx.x, wa0.x);
                fma2(accB[j], xx.x, wa0.y);
                fma2(accA[j], xx.y, wa1.x);
                fma2(accB[j], xx.y, wa1.y);
                fma2(accA[j], yy.x, wb0.x);
                fma2(accB[j], yy.x, wb0.y);
                fma2(accA[j], yy.y, wb1.x);
                fma2(accB[j], yy.y, wb1.y);
            }
        }
#pragma unroll
        for (int j = 0; j < 8; ++j) {
            float2 a = unpack2(accA[j]), bb = unpack2(accB[j]);
            *(float2*)&shP[c4][j][d2] = make_float2(a.x + a.y, bb.x + bb.y);
        }
    }
    __syncthreads();

    // reduce + leaky + pairwise shfl
    {
        float rx = 0.f, ry = 0.f, rz = 0.f, rw = 0.f;
#pragma unroll
        for (int c = 0; c < 4; ++c) {
            float4 p = *(float4*)&shP[c][g16][d4];
            rx += p.x; ry += p.y; rz += p.z; rw += p.w;
        }
        rx = leaky(rx); ry = leaky(ry); rz = leaky(rz); rw = leaky(rw);
        rx += __shfl_down_sync(0xffffffffu, rx, 16);
        ry += __shfl_down_sync(0xffffffffu, ry, 16);
        rz += __shfl_down_sync(0xffffffffu, rz, 16);
        rw += __shfl_down_sync(0xffffffffu, rw, 16);
        if ((t & 16) == 0)
            *(float4*)&shL[t >> 5][d4] = make_float4(rx, ry, rz, rw);
    }
    __syncthreads();

    // i-avg
    if (t < 16) {
        int dd = t * 4;
        float Tx = 0.f, Ty = 0.f, Tz = 0.f, Tw = 0.f;
#pragma unroll
        for (int wi = 0; wi < 4; ++wi) {
            float4 l = *(float4*)&shL[wi][dd];
            Tx += l.x; Ty += l.y; Tz += l.z; Tw += l.w;
        }
        float w1 = avgw(c1u);
        *(float4*)&shX[dd] = make_float4(Tx * w1, Ty * w1, Tz * w1, Tw * w1);
    }
    __syncthreads();

    // emb_user matvec W1u (1 row)
    {
        const __half* W1t = g_Wt2 + 7 * 4096;
        ull accA = 0ull, accB = 0ull;
#pragma unroll
        for (int q = 0; q < 4; ++q) {
            int e = c4 * 16 + q * 4;
            int ep = e >> 1;
            ulonglong2 w0 = ldw4(W1t + ep * 128 + woff);
            ulonglong2 w1 = ldw4(W1t + (ep + 1) * 128 + woff);
            ulonglong2 xx = *(const ulonglong2*)&shX[e];
            fma2(accA, xx.x, w0.x);
            fma2(accB, xx.x, w0.y);
            fma2(accA, xx.y, w1.x);
            fma2(accB, xx.y, w1.y);
        }
        float2 a = unpack2(accA), bb = unpack2(accB);
        *(float2*)&shP[c4][0][d2] = make_float2(a.x + a.y, bb.x + bb.y);
    }
    __syncthreads();

    // final reduce + dot with emb_dise
    if (t < 16) {
        int dd = t * 4;
        float rx = 0.f, ry = 0.f, rz = 0.f, rw = 0.f;
#pragma unroll
        for (int c = 0; c < 4; ++c) {
            float4 p = *(float4*)&shP[c][0][dd];
            rx += p.x; ry += p.y; rz += p.z; rw += p.w;
        }
        float v = leaky(rx) * dz.x + leaky(ry) * dz.y +
                  leaky(rz) * dz.z + leaky(rw) * dz.w;
        v += __shfl_down_sync(0x0000ffffu, v, 8, 16);
        v += __shfl_down_sync(0x0000ffffu, v, 4, 16);
        v += __shfl_down_sync(0x0000ffffu, v, 2, 16);
        v += __shfl_down_sync(0x0000ffffu, v, 1, 16);
        if (t == 0) out[b] = v;
    }
}

// ---------------------------------------------------------------------------
extern "C" void kernel_launch(void* const* d_in, const int* in_sizes, int n_in,
                              void* d_out, int out_size) {
    const float* E_s = (const float*)d_in[0];
    const float* E_d = (const float*)d_in[1];
    // weights: W_dsd_21, W_dsd_22, W_dsd_11, W_dsd_12, W_usu_3, W_usu_21, W_usu_22, W_usu_1
    k_prep<<<PREP_GRID, 256>>>(E_s, E_d,
                               (const float*)d_in[2], (const float*)d_in[3],
                               (const float*)d_in[4], (const float*)d_in[5],
                               (const float*)d_in[6], (const float*)d_in[7],
                               (const float*)d_in[8], (const float*)d_in[9]);

    k_inner<<<NB * 9, 128>>>((const int*)d_in[10], (const int*)d_in[11],
                             (const int*)d_in[12], (const int*)d_in[13],
                             (const int*)d_in[14], (const int*)d_in[15],
                             (float*)d_out);
}

// round 14
// speedup vs baseline: 1.1102x; 1.1102x over previous
#include <cuda_runtime.h>
#include <cuda_fp16.h>

#define D 64
#define NB 1024
#define XS 68   // float smem row stride (272B, 16B-aligned)

#define NS_ROWS 50001   // E_s rows
#define ND_ROWS 2001    // E_d rows

// Scratch (allocation-free rule: __device__ globals)
__device__ __align__(16) __half g_Wt2[8 * D * D];    // fp16 Wt[m][e*64+d]
__device__ __align__(16) __half g_Es2[NS_ROWS * D];  // fp16 E_s (6.4MB)
__device__ __align__(16) __half g_Ed2[ND_ROWS * D];  // fp16 E_d
__device__ __align__(16) float g_UA[NB * 8 * D];     // u1 + S
__device__ __align__(16) float g_UB[NB * 8 * D];     // S * u1
__device__ __align__(16) float g_dise[NB * D];       // emb_dise
__device__ int g_cnt[NB];                            // completion counters

typedef unsigned long long ull;

__device__ __forceinline__ float leaky(float x) { return fmaxf(x, 0.2f * x); }
__device__ __forceinline__ float avgw(int cnt)  { return cnt > 0 ? 1.0f / ((float)cnt + 1e-8f) : 0.0f; }

__device__ __forceinline__ ull pack2(float x, float y) {
    ull r; asm("mov.b64 %0, {%1, %2};" : "=l"(r) : "f"(x), "f"(y)); return r;
}
__device__ __forceinline__ float2 unpack2(ull v) {
    float2 f; asm("mov.b64 {%0, %1}, %2;" : "=f"(f.x), "=f"(f.y) : "l"(v)); return f;
}
__device__ __forceinline__ void fma2(ull& acc, ull a, ull b) {
    asm("fma.rn.f32x2 %0, %1, %2, %3;" : "=l"(acc) : "l"(a), "l"(b), "l"(acc));
}

// load 4 halves (8B) and widen to float4
__device__ __forceinline__ float4 ldh4(const __half* p) {
    uint2 raw = *(const uint2*)p;
    __half2 h0 = *reinterpret_cast<__half2*>(&raw.x);
    __half2 h1 = *reinterpret_cast<__half2*>(&raw.y);
    float2 a = __half22float2(h0), b = __half22float2(h1);
    return make_float4(a.x, a.y, b.x, b.y);
}

// load 2 fp16 weights (4B = 1 wavefront/warp) and widen+pack to fma2 operand
__device__ __forceinline__ ull ldw2(const __half* p) {
    __half2 h = *(const __half2*)p;
    float2 f = __half22float2(h);
    return pack2(f.x, f.y);
}

// ---------------------------------------------------------------------------
// K0: prep — fp16 conversion of E_s/E_d, fp16 weight transpose, counters
// ---------------------------------------------------------------------------
#define CV_S ((NS_ROWS * D / 4 + 255) / 256)   // 3126
#define CV_D ((ND_ROWS * D / 4 + 255) / 256)   // 126
#define TP_B 64
#define CN_B 4
#define PREP_GRID (CV_S + CV_D + TP_B + CN_B)

__global__ void __launch_bounds__(256)
k_prep(const float* __restrict__ E_s, const float* __restrict__ E_d,
       const float* __restrict__ w0, const float* __restrict__ w1,
       const float* __restrict__ w2, const float* __restrict__ w3,
       const float* __restrict__ w4, const float* __restrict__ w5,
       const float* __restrict__ w6, const float* __restrict__ w7) {
    int bid = blockIdx.x, t = threadIdx.x;
    if (bid < CV_S) {
        int i = bid * 256 + t;
        if (i < NS_ROWS * D / 4) {
            float4 v = *(const float4*)(E_s + i * 4);
            __half2 h0 = __floats2half2_rn(v.x, v.y);
            __half2 h1 = __floats2half2_rn(v.z, v.w);
            uint2 u;
            u.x = *reinterpret_cast<unsigned*>(&h0);
            u.y = *reinterpret_cast<unsigned*>(&h1);
            *(uint2*)(g_Es2 + i * 4) = u;
        }
    } else if (bid < CV_S + CV_D) {
        int i = (bid - CV_S) * 256 + t;
        if (i < ND_ROWS * D / 4) {
            float4 v = *(const float4*)(E_d + i * 4);
            __half2 h0 = __floats2half2_rn(v.x, v.y);
            __half2 h1 = __floats2half2_rn(v.z, v.w);
            uint2 u;
            u.x = *reinterpret_cast<unsigned*>(&h0);
            u.y = *reinterpret_cast<unsigned*>(&h1);
            *(uint2*)(g_Ed2 + i * 4) = u;
        }
    } else if (bid < CV_S + CV_D + TP_B) {
        const float* Ws[8] = {w0, w1, w2, w3, w4, w5, w6, w7};
        int k = (bid - CV_S - CV_D) * 256 + t;   // [0, 16384)
#pragma unroll
        for (int p = 0; p < 2; ++p) {
            int idx = k + p * 16384;             // linear: m,d,e
            int m = idx >> 12, de = idx & 4095;
            int d = de >> 6, e = de & 63;
            g_Wt2[m * D * D + e * D + d] = __float2half_rn(Ws[m][d * D + e]);
        }
    } else {
        int i = (bid - CV_S - CV_D - TP_B) * 256 + t;
        g_cnt[i] = 0;
    }
}

// ---------------------------------------------------------------------------
// K1: blocks [0, NB): dsd per b.  blocks [NB, 9*NB): usu inner per (b,g).
// 128 threads. Gather: fp16 rows (1 wavefront/row). Matvec: 4 warp-chunks x
// 32 lanes (2 dims), float4-LDS + register dup, fp16 weights (1 wf/load).
// 9th finisher per b runs finalization in place. 8 blocks/SM target.
// ---------------------------------------------------------------------------
__global__ void __launch_bounds__(128, 8)
k_inner(const int* __restrict__ label,
        const int* __restrict__ dsd_1, const int* __restrict__ dsd_2,
        const int* __restrict__ usu_1, const int* __restrict__ usu_2,
        const int* __restrict__ usu_3, float* __restrict__ out) {
    int t = threadIdx.x;
    int g16 = t >> 4, lane = t & 15, d4 = lane * 4;
    int c4 = t >> 5, d2 = (t & 31) * 2;

    __shared__ __align__(16) float shX[8 * XS];
    __shared__ __align__(16) float shY[8 * XS];
    __shared__ float shP[4][8][D];
    __shared__ float shL[4][XS];
    __shared__ int sFin;

    int b;

    if (blockIdx.x >= NB) {
        // ===================== usu inner: one (b,g) per block ================
        int bg = blockIdx.x - NB;
        b = bg >> 3;

        float4 u = make_float4(0.f, 0.f, 0.f, 0.f);
        int c2 = 0;
        if (t < 16) {
            int iu = __ldg(usu_1 + bg);
            u = ldh4(g_Es2 + iu * D + t * 4);
            int4 m0 = __ldg((const int4*)(usu_2 + bg * 8));
            int4 m1 = __ldg((const int4*)(usu_2 + bg * 8 + 4));
            c2 = (m0.x != 0) + (m0.y != 0) + (m0.z != 0) + (m0.w != 0)
               + (m1.x != 0) + (m1.y != 0) + (m1.z != 0) + (m1.w != 0);
        }

        const int4* ip = (const int4*)(usu_3 + (bg * 8 + g16) * 16);
        int4 i0 = __ldg(ip), i1 = __ldg(ip + 1), i2 = __ldg(ip + 2), i3 = __ldg(ip + 3);
        int cnt = (i0.x != 0) + (i0.y != 0) + (i0.z != 0) + (i0.w != 0)
                + (i1.x != 0) + (i1.y != 0) + (i1.z != 0) + (i1.w != 0)
                + (i2.x != 0) + (i2.y != 0) + (i2.z != 0) + (i2.w != 0)
                + (i3.x != 0) + (i3.y != 0) + (i3.z != 0) + (i3.w != 0);

        float sx = 0.f, sy = 0.f, sz = 0.f, sw = 0.f;
#define ACC(ix) { float4 v = ldh4(g_Es2 + (ix) * D + d4); \
                  sx += v.x; sy += v.y; sz += v.z; sw += v.w; }
        ACC(i0.x) ACC(i0.y) ACC(i0.z) ACC(i0.w)
        ACC(i1.x) ACC(i1.y) ACC(i1.z) ACC(i1.w)
        ACC(i2.x) ACC(i2.y) ACC(i2.z) ACC(i2.w)
        ACC(i3.x) ACC(i3.y) ACC(i3.z) ACC(i3.w)
#undef ACC
        float w = avgw(cnt);
        *(float4*)&shX[g16 * XS + d4] = make_float4(sx * w, sy * w, sz * w, sw * w);
        __syncthreads();

        // matvec W3: warp-chunk c4 (16 e = 4 quads), dims d2..d2+1, 8 rows
        {
            const __half* W3t = g_Wt2 + 4 * D * D;
            ull acc[8];
#pragma unroll
            for (int j = 0; j < 8; ++j) acc[j] = 0ull;
#pragma unroll
            for (int ep = 0; ep < 4; ++ep) {
                int e = c4 * 16 + ep * 4;
                ull w0 = ldw2(W3t + (e + 0) * D + d2);
                ull w1 = ldw2(W3t + (e + 1) * D + d2);
                ull w2 = ldw2(W3t + (e + 2) * D + d2);
                ull w3 = ldw2(W3t + (e + 3) * D + d2);
#pragma unroll
                for (int j = 0; j < 8; ++j) {
                    float4 xv = *(const float4*)&shX[j * XS + e];
                    fma2(acc[j], pack2(xv.x, xv.x), w0);
                    fma2(acc[j], pack2(xv.y, xv.y), w1);
                    fma2(acc[j], pack2(xv.z, xv.z), w2);
                    fma2(acc[j], pack2(xv.w, xv.w), w3);
                }
            }
#pragma unroll
            for (int j = 0; j < 8; ++j)
                *(float2*)&shP[c4][j][d2] = unpack2(acc[j]);
        }
        __syncthreads();

        // reduce 4 chunks + leaky + pairwise j via shfl
        {
            float rx = 0.f, ry = 0.f, rz = 0.f, rw = 0.f;
#pragma unroll
            for (int c = 0; c < 4; ++c) {
                float4 p = *(float4*)&shP[c][g16][d4];
                rx += p.x; ry += p.y; rz += p.z; rw += p.w;
            }
            rx = leaky(rx); ry = leaky(ry); rz = leaky(rz); rw = leaky(rw);
            rx += __shfl_down_sync(0xffffffffu, rx, 16);
            ry += __shfl_down_sync(0xffffffffu, ry, 16);
            rz += __shfl_down_sync(0xffffffffu, rz, 16);
            rw += __shfl_down_sync(0xffffffffu, rw, 16);
            if ((t & 16) == 0)
                *(float4*)&shL[t >> 5][d4] = make_float4(rx, ry, rz, rw);
        }
        __syncthreads();

        if (t < 16) {
            int dd = t * 4;
            float Sx = 0.f, Sy = 0.f, Sz = 0.f, Sw = 0.f;
#pragma unroll
            for (int wi = 0; wi < 4; ++wi) {
                float4 l = *(float4*)&shL[wi][dd];
                Sx += l.x; Sy += l.y; Sz += l.z; Sw += l.w;
            }
            float w2 = avgw(c2);
            Sx *= w2; Sy *= w2; Sz *= w2; Sw *= w2;
            *(float4*)&g_UA[bg * D + dd] = make_float4(u.x + Sx, u.y + Sy, u.z + Sz, u.w + Sw);
            *(float4*)&g_UB[bg * D + dd] = make_float4(Sx * u.x, Sy * u.y, Sz * u.z, Sw * u.w);
            __threadfence();
        }
        __syncthreads();
    } else {
        // ===================== dsd full path: one b per block ================
        b = blockIdx.x;

        float4 td4 = make_float4(0.f, 0.f, 0.f, 0.f);
        int c1 = 0;
        if (t < 16) {
            int lb = __ldg(label + b);
            td4 = ldh4(g_Ed2 + lb * D + t * 4);
            int4 m0 = __ldg((const int4*)(dsd_1 + b * 8));
            int4 m1 = __ldg((const int4*)(dsd_1 + b * 8 + 4));
            c1 = (m0.x != 0) + (m0.y != 0) + (m0.z != 0) + (m0.w != 0)
               + (m1.x != 0) + (m1.y != 0) + (m1.z != 0) + (m1.w != 0);
        }

        int ies = __ldg(dsd_1 + b * 8 + g16);
        const int4* ip = (const int4*)(dsd_2 + (b * 8 + g16) * 8);
        int4 i0 = __ldg(ip), i1 = __ldg(ip + 1);
        int cnt = (i0.x != 0) + (i0.y != 0) + (i0.z != 0) + (i0.w != 0)
                + (i1.x != 0) + (i1.y != 0) + (i1.z != 0) + (i1.w != 0);

        float4 es = ldh4(g_Es2 + ies * D + d4);
        float sx = 0.f, sy = 0.f, sz = 0.f, sw = 0.f;
#define ACC(ix) { float4 v = ldh4(g_Ed2 + (ix) * D + d4); \
                  sx += v.x; sy += v.y; sz += v.z; sw += v.w; }
        ACC(i0.x) ACC(i0.y) ACC(i0.z) ACC(i0.w)
        ACC(i1.x) ACC(i1.y) ACC(i1.z) ACC(i1.w)
#undef ACC
        float w = avgw(cnt);
        float ax = sx * w, ay = sy * w, az = sz * w, aw = sw * w;
        *(float4*)&shX[g16 * XS + d4] = make_float4(es.x + ax, es.y + ay, es.z + az, es.w + aw);
        *(float4*)&shY[g16 * XS + d4] = make_float4(ax * es.x, ay * es.y, az * es.z, aw * es.w);
        __syncthreads();

        // hop1 dual matvec W21/W22
        {
            const __half* W21t = g_Wt2 + 0 * D * D;
            const __half* W22t = g_Wt2 + 1 * D * D;
            ull acc[8];
#pragma unroll
            for (int j = 0; j < 8; ++j) acc[j] = 0ull;
#pragma unroll
            for (int ep = 0; ep < 4; ++ep) {
                int e = c4 * 16 + ep * 4;
                ull wa0 = ldw2(W21t + (e + 0) * D + d2);
                ull wa1 = ldw2(W21t + (e + 1) * D + d2);
                ull wa2 = ldw2(W21t + (e + 2) * D + d2);
                ull wa3 = ldw2(W21t + (e + 3) * D + d2);
                ull wb0 = ldw2(W22t + (e + 0) * D + d2);
                ull wb1 = ldw2(W22t + (e + 1) * D + d2);
                ull wb2 = ldw2(W22t + (e + 2) * D + d2);
                ull wb3 = ldw2(W22t + (e + 3) * D + d2);
#pragma unroll
                for (int j = 0; j < 8; ++j) {
                    float4 xv = *(const float4*)&shX[j * XS + e];
                    float4 yv = *(const float4*)&shY[j * XS + e];
                    fma2(acc[j], pack2(xv.x, xv.x), wa0);
                    fma2(acc[j], pack2(xv.y, xv.y), wa1);
                    fma2(acc[j], pack2(xv.z, xv.z), wa2);
                    fma2(acc[j], pack2(xv.w, xv.w), wa3);
                    fma2(acc[j], pack2(yv.x, yv.x), wb0);
                    fma2(acc[j], pack2(yv.y, yv.y), wb1);
                    fma2(acc[j], pack2(yv.z, yv.z), wb2);
                    fma2(acc[j], pack2(yv.w, yv.w), wb3);
                }
            }
#pragma unroll
            for (int j = 0; j < 8; ++j)
                *(float2*)&shP[c4][j][d2] = unpack2(acc[j]);
        }
        __syncthreads();

        // reduce + leaky + pairwise shfl
        {
            float rx = 0.f, ry = 0.f, rz = 0.f, rw = 0.f;
#pragma unroll
            for (int c = 0; c < 4; ++c) {
                float4 p = *(float4*)&shP[c][g16][d4];
                rx += p.x; ry += p.y; rz += p.z; rw += p.w;
            }
            rx = leaky(rx); ry = leaky(ry); rz = leaky(rz); rw = leaky(rw);
            rx += __shfl_down_sync(0xffffffffu, rx, 16);
            ry += __shfl_down_sync(0xffffffffu, ry, 16);
            rz += __shfl_down_sync(0xffffffffu, rz, 16);
            rw += __shfl_down_sync(0xffffffffu, rw, 16);
            if ((t & 16) == 0)
                *(float4*)&shL[t >> 5][d4] = make_float4(rx, ry, rz, rw);
        }
        __syncthreads();

        // hop2 inputs
        if (t < 16) {
            int dd = t * 4;
            float Ax = 0.f, Ay = 0.f, Az = 0.f, Aw = 0.f;
#pragma unroll
            for (int wi = 0; wi < 4; ++wi) {
                float4 l = *(float4*)&shL[wi][dd];
                Ax += l.x; Ay += l.y; Az += l.z; Aw += l.w;
            }
            float w1 = avgw(c1);
            Ax *= w1; Ay *= w1; Az *= w1; Aw *= w1;
            *(float4*)&shX[dd] = make_float4(Ax + td4.x, Ay + td4.y, Az + td4.z, Aw + td4.w);
            *(float4*)&shY[dd] = make_float4(Ax * td4.x, Ay * td4.y, Az * td4.z, Aw * td4.w);
        }
        __syncthreads();

        // hop2 dual matvec W11/W12 (1 row)
        {
            const __half* W11t = g_Wt2 + 2 * D * D;
            const __half* W12t = g_Wt2 + 3 * D * D;
            ull acc = 0ull;
#pragma unroll
            for (int ep = 0; ep < 4; ++ep) {
                int e = c4 * 16 + ep * 4;
                float4 xv = *(const float4*)&shX[e];
                float4 yv = *(const float4*)&shY[e];
                fma2(acc, pack2(xv.x, xv.x), ldw2(W11t + (e + 0) * D + d2));
                fma2(acc, pack2(xv.y, xv.y), ldw2(W11t + (e + 1) * D + d2));
                fma2(acc, pack2(xv.z, xv.z), ldw2(W11t + (e + 2) * D + d2));
                fma2(acc, pack2(xv.w, xv.w), ldw2(W11t + (e + 3) * D + d2));
                fma2(acc, pack2(yv.x, yv.x), ldw2(W12t + (e + 0) * D + d2));
                fma2(acc, pack2(yv.y, yv.y), ldw2(W12t + (e + 1) * D + d2));
                fma2(acc, pack2(yv.z, yv.z), ldw2(W12t + (e + 2) * D + d2));
                fma2(acc, pack2(yv.w, yv.w), ldw2(W12t + (e + 3) * D + d2));
            }
            *(float2*)&shP[c4][0][d2] = unpack2(acc);
        }
        __syncthreads();

        if (t < 16) {
            int dd = t * 4;
            float rx = 0.f, ry = 0.f, rz = 0.f, rw = 0.f;
#pragma unroll
            for (int c = 0; c < 4; ++c) {
                float4 p = *(float4*)&shP[c][0][dd];
                rx += p.x; ry += p.y; rz += p.z; rw += p.w;
            }
            *(float4*)&g_dise[b * D + dd] =
                make_float4(leaky(rx), leaky(ry), leaky(rz), leaky(rw));
            __threadfence();
        }
        __syncthreads();
    }

    // ======================= completion + finalization =======================
    if (t == 0) {
        int old = atomicAdd(&g_cnt[b], 1);
        if (old == 8) { __threadfence(); sFin = 1; } else sFin = 0;
    }
    __syncthreads();
    if (!sFin) return;

    // --- finalization: es1 matvec + i-avg + W1u matvec + dot with dise ---
    float4 dz = make_float4(0.f, 0.f, 0.f, 0.f);
    int c1u = 0;
    if (t < 16) {
        dz = *(const float4*)&g_dise[b * D + t * 4];
        int4 m0 = __ldg((const int4*)(usu_1 + b * 8));
        int4 m1 = __ldg((const int4*)(usu_1 + b * 8 + 4));
        c1u = (m0.x != 0) + (m0.y != 0) + (m0.z != 0) + (m0.w != 0)
            + (m1.x != 0) + (m1.y != 0) + (m1.z != 0) + (m1.w != 0);
    }
    *(float4*)&shX[g16 * XS + d4] = *(const float4*)&g_UA[(b * 8 + g16) * D + d4];
    *(float4*)&shY[g16 * XS + d4] = *(const float4*)&g_UB[(b * 8 + g16) * D + d4];
    __syncthreads();

    // es1 dual matvec W21u/W22u
    {
        const __half* W21t = g_Wt2 + 5 * D * D;
        const __half* W22t = g_Wt2 + 6 * D * D;
        ull acc[8];
#pragma unroll
        for (int j = 0; j < 8; ++j) acc[j] = 0ull;
#pragma unroll
        for (int ep = 0; ep < 4; ++ep) {
            int e = c4 * 16 + ep * 4;
            ull wa0 = ldw2(W21t + (e + 0) * D + d2);
            ull wa1 = ldw2(W21t + (e + 1) * D + d2);
            ull wa2 = ldw2(W21t + (e + 2) * D + d2);
            ull wa3 = ldw2(W21t + (e + 3) * D + d2);
            ull wb0 = ldw2(W22t + (e + 0) * D + d2);
            ull wb1 = ldw2(W22t + (e + 1) * D + d2);
            ull wb2 = ldw2(W22t + (e + 2) * D + d2);
            ull wb3 = ldw2(W22t + (e + 3) * D + d2);
#pragma unroll
            for (int j = 0; j < 8; ++j) {
                float4 xv = *(const float4*)&shX[j * XS + e];
                float4 yv = *(const float4*)&shY[j * XS + e];
                fma2(acc[j], pack2(xv.x, xv.x), wa0);
                fma2(acc[j], pack2(xv.y, xv.y), wa1);
                fma2(acc[j], pack2(xv.z, xv.z), wa2);
                fma2(acc[j], pack2(xv.w, xv.w), wa3);
                fma2(acc[j], pack2(yv.x, yv.x), wb0);
                fma2(acc[j], pack2(yv.y, yv.y), wb1);
                fma2(acc[j], pack2(yv.z, yv.z), wb2);
                fma2(acc[j], pack2(yv.w, yv.w), wb3);
            }
        }
#pragma unroll
        for (int j = 0; j < 8; ++j)
            *(float2*)&shP[c4][j][d2] = unpack2(acc[j]);
    }
    __syncthreads();

    // reduce + leaky + pairwise shfl
    {
        float rx = 0.f, ry = 0.f, rz = 0.f, rw = 0.f;
#pragma unroll
        for (int c = 0; c < 4; ++c) {
            float4 p = *(float4*)&shP[c][g16][d4];
            rx += p.x; ry += p.y; rz += p.z; rw += p.w;
        }
        rx = leaky(rx); ry = leaky(ry); rz = leaky(rz); rw = leaky(rw);
        rx += __shfl_down_sync(0xffffffffu, rx, 16);
        ry += __shfl_down_sync(0xffffffffu, ry, 16);
        rz += __shfl_down_sync(0xffffffffu, rz, 16);
        rw += __shfl_down_sync(0xffffffffu, rw, 16);
        if ((t & 16) == 0)
            *(float4*)&shL[t >> 5][d4] = make_float4(rx, ry, rz, rw);
    }
    __syncthreads();

    // i-avg
    if (t < 16) {
        int dd = t * 4;
        float Tx = 0.f, Ty = 0.f, Tz = 0.f, Tw = 0.f;
#pragma unroll
        for (int wi = 0; wi < 4; ++wi) {
            float4 l = *(float4*)&shL[wi][dd];
            Tx += l.x; Ty += l.y; Tz += l.z; Tw += l.w;
        }
        float w1 = avgw(c1u);
        *(float4*)&shX[dd] = make_float4(Tx * w1, Ty * w1, Tz * w1, Tw * w1);
    }
    __syncthreads();

    // emb_user matvec W1u (1 row)
    {
        const __half* W1t = g_Wt2 + 7 * D * D;
        ull acc = 0ull;
#pragma unroll
        for (int ep = 0; ep < 4; ++ep) {
            int e = c4 * 16 + ep * 4;
            float4 xv = *(const float4*)&shX[e];
            fma2(acc, pack2(xv.x, xv.x), ldw2(W1t + (e + 0) * D + d2));
            fma2(acc, pack2(xv.y, xv.y), ldw2(W1t + (e + 1) * D + d2));
            fma2(acc, pack2(xv.z, xv.z), ldw2(W1t + (e + 2) * D + d2));
            fma2(acc, pack2(xv.w, xv.w), ldw2(W1t + (e + 3) * D + d2));
        }
        *(float2*)&shP[c4][0][d2] = unpack2(acc);
    }
    __syncthreads();

    // final reduce + dot with emb_dise
    if (t < 16) {
        int dd = t * 4;
        float rx = 0.f, ry = 0.f, rz = 0.f, rw = 0.f;
#pragma unroll
        for (int c = 0; c < 4; ++c) {
            float4 p = *(float4*)&shP[c][0][dd];
            rx += p.x; ry += p.y; rz += p.z; rw += p.w;
        }
        float v = leaky(rx) * dz.x + leaky(ry) * dz.y +
                  leaky(rz) * dz.z + leaky(rw) * dz.w;
        v += __shfl_down_sync(0x0000ffffu, v, 8, 16);
        v += __shfl_down_sync(0x0000ffffu, v, 4, 16);
        v += __shfl_down_sync(0x0000ffffu, v, 2, 16);
        v += __shfl_down_sync(0x0000ffffu, v, 1, 16);
        if (t == 0) out[b] = v;
    }
}

// ---------------------------------------------------------------------------
extern "C" void kernel_launch(void* const* d_in, const int* in_sizes, int n_in,
                              void* d_out, int out_size) {
    const float* E_s = (const float*)d_in[0];
    const float* E_d = (const float*)d_in[1];
    // weights: W_dsd_21, W_dsd_22, W_dsd_11, W_dsd_12, W_usu_3, W_usu_21, W_usu_22, W_usu_1
    k_prep<<<PREP_GRID, 256>>>(E_s, E_d,
                               (const float*)d_in[2], (const float*)d_in[3],
                               (const float*)d_in[4], (const float*)d_in[5],
                               (const float*)d_in[6], (const float*)d_in[7],
                               (const float*)d_in[8], (const float*)d_in[9]);

    k_inner<<<NB * 9, 128>>>((const int*)d_in[10], (const int*)d_in[11],
                             (const int*)d_in[12], (const int*)d_in[13],
                             (const int*)d_in[14], (const int*)d_in[15],
                             (float*)d_out);
}

// round 15
// speedup vs baseline: 1.2246x; 1.1031x over previous
#include <cuda_runtime.h>
#include <cuda_fp16.h>

#define D 64
#define NB 1024
#define XS 68    // float smem row stride
#define XH 88    // half smem row stride for HMMA tile (176B: 16B-aligned, conflict-free rows)

#define NS_ROWS 50001
#define ND_ROWS 2001

// Scratch (allocation-free rule: __device__ globals)
__device__ __align__(16) __half g_Wt2[8 * D * D];    // fp16 Wt[m][e*64+d] (scalar matvec paths)
__device__ __align__(16) unsigned g_W3f[4 * 4 * 32 * 4]; // W3 A-fragments [mc][kc][lane][4xu32]
__device__ __align__(16) __half g_Es2[NS_ROWS * D];
__device__ __align__(16) __half g_Ed2[ND_ROWS * D];
__device__ __align__(16) float g_UA[NB * 8 * D];
__device__ __align__(16) float g_UB[NB * 8 * D];
__device__ __align__(16) float g_dise[NB * D];
__device__ int g_cnt[NB];

typedef unsigned long long ull;

__device__ __forceinline__ float leaky(float x) { return fmaxf(x, 0.2f * x); }
__device__ __forceinline__ float avgw(int cnt)  { return cnt > 0 ? 1.0f / ((float)cnt + 1e-8f) : 0.0f; }

__device__ __forceinline__ ull pack2(float x, float y) {
    ull r; asm("mov.b64 %0, {%1, %2};" : "=l"(r) : "f"(x), "f"(y)); return r;
}
__device__ __forceinline__ float2 unpack2(ull v) {
    float2 f; asm("mov.b64 {%0, %1}, %2;" : "=f"(f.x), "=f"(f.y) : "l"(v)); return f;
}
__device__ __forceinline__ void fma2(ull& acc, ull a, ull b) {
    asm("fma.rn.f32x2 %0, %1, %2, %3;" : "=l"(acc) : "l"(a), "l"(b), "l"(acc));
}

__device__ __forceinline__ float4 ldh4(const __half* p) {
    uint2 raw = *(const uint2*)p;
    __half2 h0 = *reinterpret_cast<__half2*>(&raw.x);
    __half2 h1 = *reinterpret_cast<__half2*>(&raw.y);
    float2 a = __half22float2(h0), b = __half22float2(h1);
    return make_float4(a.x, a.y, b.x, b.y);
}

__device__ __forceinline__ ull ldw2(const __half* p) {
    __half2 h = *(const __half2*)p;
    float2 f = __half22float2(h);
    return pack2(f.x, f.y);
}

__device__ __forceinline__ unsigned h2bits(__half2 h) {
    return *reinterpret_cast<unsigned*>(&h);
}

// ---------------------------------------------------------------------------
// K0: prep — fp16 E_s/E_d, fp16 weight transpose, W3 MMA fragments, counters
// ---------------------------------------------------------------------------
#define CV_S ((NS_ROWS * D / 4 + 255) / 256)   // 3126
#define CV_D ((ND_ROWS * D / 4 + 255) / 256)   // 126
#define TP_B 64
#define FR_B 2
#define CN_B 4
#define PREP_GRID (CV_S + CV_D + TP_B + FR_B + CN_B)

__global__ void __launch_bounds__(256)
k_prep(const float* __restrict__ E_s, const float* __restrict__ E_d,
       const float* __restrict__ w0, const float* __restrict__ w1,
       const float* __restrict__ w2, const float* __restrict__ w3,
       const float* __restrict__ w4, const float* __restrict__ w5,
       const float* __restrict__ w6, const float* __restrict__ w7) {
    int bid = blockIdx.x, t = threadIdx.x;
    if (bid < CV_S) {
        int i = bid * 256 + t;
        if (i < NS_ROWS * D / 4) {
            float4 v = *(const float4*)(E_s + i * 4);
            uint2 u;
            u.x = h2bits(__floats2half2_rn(v.x, v.y));
            u.y = h2bits(__floats2half2_rn(v.z, v.w));
            *(uint2*)(g_Es2 + i * 4) = u;
        }
    } else if (bid < CV_S + CV_D) {
        int i = (bid - CV_S) * 256 + t;
        if (i < ND_ROWS * D / 4) {
            float4 v = *(const float4*)(E_d + i * 4);
            uint2 u;
            u.x = h2bits(__floats2half2_rn(v.x, v.y));
            u.y = h2bits(__floats2half2_rn(v.z, v.w));
            *(uint2*)(g_Ed2 + i * 4) = u;
        }
    } else if (bid < CV_S + CV_D + TP_B) {
        const float* Ws[8] = {w0, w1, w2, w3, w4, w5, w6, w7};
        int k = (bid - CV_S - CV_D) * 256 + t;
#pragma unroll
        for (int p = 0; p < 2; ++p) {
            int idx = k + p * 16384;
            int m = idx >> 12, de = idx & 4095;
            int d = de >> 6, e = de & 63;
            g_Wt2[m * D * D + e * D + d] = __float2half_rn(Ws[m][d * D + e]);
        }
    } else if (bid < CV_S + CV_D + TP_B + FR_B) {
        // W3 A-fragments for mma.m16n8k16.row.col: A = W3 (row=d, col=e)
        int idx = (bid - CV_S - CV_D - TP_B) * 256 + t;   // 0..511
        if (idx < 512) {
            int mc = idx >> 7, kc = (idx >> 5) & 3, lane = idx & 31;
            int d = mc * 16 + (lane >> 2);
            int e = kc * 16 + (lane & 3) * 2;
            const float* W = w4;   // W_usu_3, row-major [d][e]
            uint4 o;
            o.x = h2bits(__floats2half2_rn(W[d * D + e],           W[d * D + e + 1]));
            o.y = h2bits(__floats2half2_rn(W[(d + 8) * D + e],     W[(d + 8) * D + e + 1]));
            o.z = h2bits(__floats2half2_rn(W[d * D + e + 8],       W[d * D + e + 9]));
            o.w = h2bits(__floats2half2_rn(W[(d + 8) * D + e + 8], W[(d + 8) * D + e + 9]));
            *(uint4*)&g_W3f[idx * 4] = o;
        }
    } else {
        int i = (bid - CV_S - CV_D - TP_B - FR_B) * 256 + t;
        g_cnt[i] = 0;
    }
}

// ---------------------------------------------------------------------------
// K1: blocks [0, NB): dsd per b (scalar path).  blocks [NB, 9*NB): usu inner
// per (b,g) with tensor-core matvec. 9th finisher per b finalizes (scalar).
// ---------------------------------------------------------------------------
__global__ void __launch_bounds__(128, 8)
k_inner(const int* __restrict__ label,
        const int* __restrict__ dsd_1, const int* __restrict__ dsd_2,
        const int* __restrict__ usu_1, const int* __restrict__ usu_2,
        const int* __restrict__ usu_3, float* __restrict__ out) {
    int t = threadIdx.x;
    int g16 = t >> 4, lane16 = t & 15, d4 = lane16 * 4;
    int c4 = t >> 5, d2 = (t & 31) * 2;
    int l31 = t & 31;

    __shared__ __align__(16) float shX[8 * XS];
    __shared__ __align__(16) float shY[8 * XS];
    __shared__ float shP[4][8][D];
    __shared__ float shL[4][XS];
    __shared__ __align__(16) __half shXh[8 * XH];   // fp16 gather tile for HMMA
    __shared__ __align__(16) float sL2[64];
    __shared__ int sFin;

    int b;

    if (blockIdx.x >= NB) {
        // ===================== usu inner: one (b,g) per block ================
        int bg = blockIdx.x - NB;
        b = bg >> 3;

        float4 u = make_float4(0.f, 0.f, 0.f, 0.f);
        int c2m = 0;
        if (t < 16) {
            int iu = __ldg(usu_1 + bg);
            u = ldh4(g_Es2 + iu * D + t * 4);
            int4 m0 = __ldg((const int4*)(usu_2 + bg * 8));
            int4 m1 = __ldg((const int4*)(usu_2 + bg * 8 + 4));
            c2m = (m0.x != 0) + (m0.y != 0) + (m0.z != 0) + (m0.w != 0)
                + (m1.x != 0) + (m1.y != 0) + (m1.z != 0) + (m1.w != 0);
        }

        const int4* ip = (const int4*)(usu_3 + (bg * 8 + g16) * 16);
        int4 i0 = __ldg(ip), i1 = __ldg(ip + 1), i2 = __ldg(ip + 2), i3 = __ldg(ip + 3);
        int cnt = (i0.x != 0) + (i0.y != 0) + (i0.z != 0) + (i0.w != 0)
                + (i1.x != 0) + (i1.y != 0) + (i1.z != 0) + (i1.w != 0)
                + (i2.x != 0) + (i2.y != 0) + (i2.z != 0) + (i2.w != 0)
                + (i3.x != 0) + (i3.y != 0) + (i3.z != 0) + (i3.w != 0);

        float sx = 0.f, sy = 0.f, sz = 0.f, sw = 0.f;
#define ACC(ix) { float4 v = ldh4(g_Es2 + (ix) * D + d4); \
                  sx += v.x; sy += v.y; sz += v.z; sw += v.w; }
        ACC(i0.x) ACC(i0.y) ACC(i0.z) ACC(i0.w)
        ACC(i1.x) ACC(i1.y) ACC(i1.z) ACC(i1.w)
        ACC(i2.x) ACC(i2.y) ACC(i2.z) ACC(i2.w)
        ACC(i3.x) ACC(i3.y) ACC(i3.z) ACC(i3.w)
#undef ACC
        float w = avgw(cnt);
        {
            uint2 hh;
            hh.x = h2bits(__floats2half2_rn(sx * w, sy * w));
            hh.y = h2bits(__floats2half2_rn(sz * w, sw * w));
            *(uint2*)&shXh[g16 * XH + d4] = hh;
        }
        __syncthreads();

        // ---- tensor-core matvec: out^T[d][j] = W3 @ X^T, warp c4 -> d slice ----
        {
            float c0 = 0.f, c1 = 0.f, c2 = 0.f, c3 = 0.f;
            unsigned baddr = (unsigned)__cvta_generic_to_shared(shXh)
                           + (unsigned)(((l31 & 7) * XH + ((l31 >> 3) & 1) * 8) * 2);
#pragma unroll
            for (int kc = 0; kc < 4; ++kc) {
                uint4 A = *(const uint4*)&g_W3f[((c4 * 4 + kc) * 32 + l31) * 4];
                unsigned ba = baddr + kc * 32;
                unsigned b0, b1;
                asm volatile("ldmatrix.sync.aligned.m8n8.x2.shared.b16 {%0,%1}, [%2];"
                             : "=r"(b0), "=r"(b1) : "r"(ba));
                asm volatile("mma.sync.aligned.m16n8k16.row.col.f32.f16.f16.f32 "
                             "{%0,%1,%2,%3}, {%4,%5,%6,%7}, {%8,%9}, {%0,%1,%2,%3};"
                             : "+f"(c0), "+f"(c1), "+f"(c2), "+f"(c3)
                             : "r"(A.x), "r"(A.y), "r"(A.z), "r"(A.w), "r"(b0), "r"(b1));
            }
            // leaky per (d, j) element, then sum over j (cols)
            float v01 = leaky(c0) + leaky(c1);
            float v23 = leaky(c2) + leaky(c3);
            v01 += __shfl_down_sync(0xffffffffu, v01, 2);
            v23 += __shfl_down_sync(0xffffffffu, v23, 2);
            v01 += __shfl_down_sync(0xffffffffu, v01, 1);
            v23 += __shfl_down_sync(0xffffffffu, v23, 1);
            if ((l31 & 3) == 0) {
                int dbase = c4 * 16 + (l31 >> 2);
                sL2[dbase] = v01;
                sL2[dbase + 8] = v23;
            }
        }
        __syncthreads();

        if (t < 16) {
            int dd = t * 4;
            float4 S = *(float4*)&sL2[dd];
            float w2 = avgw(c2m);
            float Sx = S.x * w2, Sy = S.y * w2, Sz = S.z * w2, Sw = S.w * w2;
            *(float4*)&g_UA[bg * D + dd] = make_float4(u.x + Sx, u.y + Sy, u.z + Sz, u.w + Sw);
            *(float4*)&g_UB[bg * D + dd] = make_float4(Sx * u.x, Sy * u.y, Sz * u.z, Sw * u.w);
            __threadfence();
        }
        __syncthreads();
    } else {
        // ===================== dsd full path: one b per block ================
        b = blockIdx.x;

        float4 td4 = make_float4(0.f, 0.f, 0.f, 0.f);
        int c1 = 0;
        if (t < 16) {
            int lb = __ldg(label + b);
            td4 = ldh4(g_Ed2 + lb * D + t * 4);
            int4 m0 = __ldg((const int4*)(dsd_1 + b * 8));
            int4 m1 = __ldg((const int4*)(dsd_1 + b * 8 + 4));
            c1 = (m0.x != 0) + (m0.y != 0) + (m0.z != 0) + (m0.w != 0)
               + (m1.x != 0) + (m1.y != 0) + (m1.z != 0) + (m1.w != 0);
        }

        int ies = __ldg(dsd_1 + b * 8 + g16);
        const int4* ip = (const int4*)(dsd_2 + (b * 8 + g16) * 8);
        int4 i0 = __ldg(ip), i1 = __ldg(ip + 1);
        int cnt = (i0.x != 0) + (i0.y != 0) + (i0.z != 0) + (i0.w != 0)
                + (i1.x != 0) + (i1.y != 0) + (i1.z != 0) + (i1.w != 0);

        float4 es = ldh4(g_Es2 + ies * D + d4);
        float sx = 0.f, sy = 0.f, sz = 0.f, sw = 0.f;
#define ACC(ix) { float4 v = ldh4(g_Ed2 + (ix) * D + d4); \
                  sx += v.x; sy += v.y; sz += v.z; sw += v.w; }
        ACC(i0.x) ACC(i0.y) ACC(i0.z) ACC(i0.w)
        ACC(i1.x) ACC(i1.y) ACC(i1.z) ACC(i1.w)
#undef ACC
        float w = avgw(cnt);
        float ax = sx * w, ay = sy * w, az = sz * w, aw = sw * w;
        *(float4*)&shX[g16 * XS + d4] = make_float4(es.x + ax, es.y + ay, es.z + az, es.w + aw);
        *(float4*)&shY[g16 * XS + d4] = make_float4(ax * es.x, ay * es.y, az * es.z, aw * es.w);
        __syncthreads();

        // hop1 dual matvec W21/W22 (scalar fma2 path)
        {
            const __half* W21t = g_Wt2 + 0 * D * D;
            const __half* W22t = g_Wt2 + 1 * D * D;
            ull acc[8];
#pragma unroll
            for (int j = 0; j < 8; ++j) acc[j] = 0ull;
#pragma unroll
            for (int ep = 0; ep < 4; ++ep) {
                int e = c4 * 16 + ep * 4;
                ull wa0 = ldw2(W21t + (e + 0) * D + d2);
                ull wa1 = ldw2(W21t + (e + 1) * D + d2);
                ull wa2 = ldw2(W21t + (e + 2) * D + d2);
                ull wa3 = ldw2(W21t + (e + 3) * D + d2);
                ull wb0 = ldw2(W22t + (e + 0) * D + d2);
                ull wb1 = ldw2(W22t + (e + 1) * D + d2);
                ull wb2 = ldw2(W22t + (e + 2) * D + d2);
                ull wb3 = ldw2(W22t + (e + 3) * D + d2);
#pragma unroll
                for (int j = 0; j < 8; ++j) {
                    float4 xv = *(const float4*)&shX[j * XS + e];
                    float4 yv = *(const float4*)&shY[j * XS + e];
                    fma2(acc[j], pack2(xv.x, xv.x), wa0);
                    fma2(acc[j], pack2(xv.y, xv.y), wa1);
                    fma2(acc[j], pack2(xv.z, xv.z), wa2);
                    fma2(acc[j], pack2(xv.w, xv.w), wa3);
                    fma2(acc[j], pack2(yv.x, yv.x), wb0);
                    fma2(acc[j], pack2(yv.y, yv.y), wb1);
                    fma2(acc[j], pack2(yv.z, yv.z), wb2);
                    fma2(acc[j], pack2(yv.w, yv.w), wb3);
                }
            }
#pragma unroll
            for (int j = 0; j < 8; ++j)
                *(float2*)&shP[c4][j][d2] = unpack2(acc[j]);
        }
        __syncthreads();

        {
            float rx = 0.f, ry = 0.f, rz = 0.f, rw = 0.f;
#pragma unroll
            for (int c = 0; c < 4; ++c) {
                float4 p = *(float4*)&shP[c][g16][d4];
                rx += p.x; ry += p.y; rz += p.z; rw += p.w;
            }
            rx = leaky(rx); ry = leaky(ry); rz = leaky(rz); rw = leaky(rw);
            rx += __shfl_down_sync(0xffffffffu, rx, 16);
            ry += __shfl_down_sync(0xffffffffu, ry, 16);
            rz += __shfl_down_sync(0xffffffffu, rz, 16);
            rw += __shfl_down_sync(0xffffffffu, rw, 16);
            if ((t & 16) == 0)
                *(float4*)&shL[t >> 5][d4] = make_float4(rx, ry, rz, rw);
        }
        __syncthreads();

        if (t < 16) {
            int dd = t * 4;
            float Ax = 0.f, Ay = 0.f, Az = 0.f, Aw = 0.f;
#pragma unroll
            for (int wi = 0; wi < 4; ++wi) {
                float4 l = *(float4*)&shL[wi][dd];
                Ax += l.x; Ay += l.y; Az += l.z; Aw += l.w;
            }
            float w1 = avgw(c1);
            Ax *= w1; Ay *= w1; Az *= w1; Aw *= w1;
            *(float4*)&shX[dd] = make_float4(Ax + td4.x, Ay + td4.y, Az + td4.z, Aw + td4.w);
            *(float4*)&shY[dd] = make_float4(Ax * td4.x, Ay * td4.y, Az * td4.z, Aw * td4.w);
        }
        __syncthreads();

        {
            const __half* W11t = g_Wt2 + 2 * D * D;
            const __half* W12t = g_Wt2 + 3 * D * D;
            ull acc = 0ull;
#pragma unroll
            for (int ep = 0; ep < 4; ++ep) {
                int e = c4 * 16 + ep * 4;
                float4 xv = *(const float4*)&shX[e];
                float4 yv = *(const float4*)&shY[e];
                fma2(acc, pack2(xv.x, xv.x), ldw2(W11t + (e + 0) * D + d2));
                fma2(acc, pack2(xv.y, xv.y), ldw2(W11t + (e + 1) * D + d2));
                fma2(acc, pack2(xv.z, xv.z), ldw2(W11t + (e + 2) * D + d2));
                fma2(acc, pack2(xv.w, xv.w), ldw2(W11t + (e + 3) * D + d2));
                fma2(acc, pack2(yv.x, yv.x), ldw2(W12t + (e + 0) * D + d2));
                fma2(acc, pack2(yv.y, yv.y), ldw2(W12t + (e + 1) * D + d2));
                fma2(acc, pack2(yv.z, yv.z), ldw2(W12t + (e + 2) * D + d2));
                fma2(acc, pack2(yv.w, yv.w), ldw2(W12t + (e + 3) * D + d2));
            }
            *(float2*)&shP[c4][0][d2] = unpack2(acc);
        }
        __syncthreads();

        if (t < 16) {
            int dd = t * 4;
            float rx = 0.f, ry = 0.f, rz = 0.f, rw = 0.f;
#pragma unroll
            for (int c = 0; c < 4; ++c) {
                float4 p = *(float4*)&shP[c][0][dd];
                rx += p.x; ry += p.y; rz += p.z; rw += p.w;
            }
            *(float4*)&g_dise[b * D + dd] =
                make_float4(leaky(rx), leaky(ry), leaky(rz), leaky(rw));
            __threadfence();
        }
        __syncthreads();
    }

    // ======================= completion + finalization =======================
    if (t == 0) {
        int old = atomicAdd(&g_cnt[b], 1);
        if (old == 8) { __threadfence(); sFin = 1; } else sFin = 0;
    }
    __syncthreads();
    if (!sFin) return;

    // --- finalization: es1 matvec + i-avg + W1u matvec + dot with dise ---
    float4 dz = make_float4(0.f, 0.f, 0.f, 0.f);
    int c1u = 0;
    if (t < 16) {
        dz = *(const float4*)&g_dise[b * D + t * 4];
        int4 m0 = __ldg((const int4*)(usu_1 + b * 8));
        int4 m1 = __ldg((const int4*)(usu_1 + b * 8 + 4));
        c1u = (m0.x != 0) + (m0.y != 0) + (m0.z != 0) + (m0.w != 0)
            + (m1.x != 0) + (m1.y != 0) + (m1.z != 0) + (m1.w != 0);
    }
    *(float4*)&shX[g16 * XS + d4] = *(const float4*)&g_UA[(b * 8 + g16) * D + d4];
    *(float4*)&shY[g16 * XS + d4] = *(const float4*)&g_UB[(b * 8 + g16) * D + d4];
    __syncthreads();

    {
        const __half* W21t = g_Wt2 + 5 * D * D;
        const __half* W22t = g_Wt2 + 6 * D * D;
        ull acc[8];
#pragma unroll
        for (int j = 0; j < 8; ++j) acc[j] = 0ull;
#pragma unroll
        for (int ep = 0; ep < 4; ++ep) {
            int e = c4 * 16 + ep * 4;
            ull wa0 = ldw2(W21t + (e + 0) * D + d2);
            ull wa1 = ldw2(W21t + (e + 1) * D + d2);
            ull wa2 = ldw2(W21t + (e + 2) * D + d2);
            ull wa3 = ldw2(W21t + (e + 3) * D + d2);
            ull wb0 = ldw2(W22t + (e + 0) * D + d2);
            ull wb1 = ldw2(W22t + (e + 1) * D + d2);
            ull wb2 = ldw2(W22t + (e + 2) * D + d2);
            ull wb3 = ldw2(W22t + (e + 3) * D + d2);
#pragma unroll
            for (int j = 0; j < 8; ++j) {
                float4 xv = *(const float4*)&shX[j * XS + e];
                float4 yv = *(const float4*)&shY[j * XS + e];
                fma2(acc[j], pack2(xv.x, xv.x), wa0);
                fma2(acc[j], pack2(xv.y, xv.y), wa1);
                fma2(acc[j], pack2(xv.z, xv.z), wa2);
                fma2(acc[j], pack2(xv.w, xv.w), wa3);
                fma2(acc[j], pack2(yv.x, yv.x), wb0);
                fma2(acc[j], pack2(yv.y, yv.y), wb1);
                fma2(acc[j], pack2(yv.z, yv.z), wb2);
                fma2(acc[j], pack2(yv.w, yv.w), wb3);
            }
        }
#pragma unroll
        for (int j = 0; j < 8; ++j)
            *(float2*)&shP[c4][j][d2] = unpack2(acc[j]);
    }
    __syncthreads();

    {
        float rx = 0.f, ry = 0.f, rz = 0.f, rw = 0.f;
#pragma unroll
        for (int c = 0; c < 4; ++c) {
            float4 p = *(float4*)&shP[c][g16][d4];
            rx += p.x; ry += p.y; rz += p.z; rw += p.w;
        }
        rx = leaky(rx); ry = leaky(ry); rz = leaky(rz); rw = leaky(rw);
        rx += __shfl_down_sync(0xffffffffu, rx, 16);
        ry += __shfl_down_sync(0xffffffffu, ry, 16);
        rz += __shfl_down_sync(0xffffffffu, rz, 16);
        rw += __shfl_down_sync(0xffffffffu, rw, 16);
        if ((t & 16) == 0)
            *(float4*)&shL[t >> 5][d4] = make_float4(rx, ry, rz, rw);
    }
    __syncthreads();

    if (t < 16) {
        int dd = t * 4;
        float Tx = 0.f, Ty = 0.f, Tz = 0.f, Tw = 0.f;
#pragma unroll
        for (int wi = 0; wi < 4; ++wi) {
            float4 l = *(float4*)&shL[wi][dd];
            Tx += l.x; Ty += l.y; Tz += l.z; Tw += l.w;
        }
        float w1 = avgw(c1u);
        *(float4*)&shX[dd] = make_float4(Tx * w1, Ty * w1, Tz * w1, Tw * w1);
    }
    __syncthreads();

    {
        const __half* W1t = g_Wt2 + 7 * D * D;
        ull acc = 0ull;
#pragma unroll
        for (int ep = 0; ep < 4; ++ep) {
            int e = c4 * 16 + ep * 4;
            float4 xv = *(const float4*)&shX[e];
            fma2(acc, pack2(xv.x, xv.x), ldw2(W1t + (e + 0) * D + d2));
            fma2(acc, pack2(xv.y, xv.y), ldw2(W1t + (e + 1) * D + d2));
            fma2(acc, pack2(xv.z, xv.z), ldw2(W1t + (e + 2) * D + d2));
            fma2(acc, pack2(xv.w, xv.w), ldw2(W1t + (e + 3) * D + d2));
        }
        *(float2*)&shP[c4][0][d2] = unpack2(acc);
    }
    __syncthreads();

    if (t < 16) {
        int dd = t * 4;
        float rx = 0.f, ry = 0.f, rz = 0.f, rw = 0.f;
#pragma unroll
        for (int c = 0; c < 4; ++c) {
            float4 p = *(float4*)&shP[c][0][dd];
            rx += p.x; ry += p.y; rz += p.z; rw += p.w;
        }
        float v = leaky(rx) * dz.x + leaky(ry) * dz.y +
                  leaky(rz) * dz.z + leaky(rw) * dz.w;
        v += __shfl_down_sync(0x0000ffffu, v, 8, 16);
        v += __shfl_down_sync(0x0000ffffu, v, 4, 16);
        v += __shfl_down_sync(0x0000ffffu, v, 2, 16);
        v += __shfl_down_sync(0x0000ffffu, v, 1, 16);
        if (t == 0) out[b] = v;
    }
}

// ---------------------------------------------------------------------------
extern "C" void kernel_launch(void* const* d_in, const int* in_sizes, int n_in,
                              void* d_out, int out_size) {
    const float* E_s = (const float*)d_in[0];
    const float* E_d = (const float*)d_in[1];
    // weights: W_dsd_21, W_dsd_22, W_dsd_11, W_dsd_12, W_usu_3, W_usu_21, W_usu_22, W_usu_1
    k_prep<<<PREP_GRID, 256>>>(E_s, E_d,
                               (const float*)d_in[2], (const float*)d_in[3],
                               (const float*)d_in[4], (const float*)d_in[5],
                               (const float*)d_in[6], (const float*)d_in[7],
                               (const float*)d_in[8], (const float*)d_in[9]);

    k_inner<<<NB * 9, 128>>>((const int*)d_in[10], (const int*)d_in[11],
                             (const int*)d_in[12], (const int*)d_in[13],
                             (const int*)d_in[14], (const int*)d_in[15],
                             (float*)d_out);
}

// round 16
// speedup vs baseline: 1.3918x; 1.1365x over previous
#include <cuda_runtime.h>
#include <cuda_fp16.h>

#define D 64
#define NB 1024
#define XS 68
#define XH2 136   // half smem row stride for HMMA tiles (272B, conflict-free)

#define NS_ROWS 50001
#define ND_ROWS 2001

// Scratch (allocation-free rule: __device__ globals)
__device__ __align__(16) __half g_Wt2[8 * D * D];        // fp16 Wt (scalar paths)
__device__ __align__(16) unsigned g_W3f[4 * 4 * 32 * 4]; // W3 A-fragments
__device__ __align__(16) unsigned g_Wcatf[2 * 4 * 8 * 32 * 4]; // [pair][mc][kc][lane][4]
__device__ __align__(16) __half g_Es2[NS_ROWS * D];
__device__ __align__(16) __half g_Ed2[ND_ROWS * D];
__device__ __align__(16) float g_UA[NB * 8 * D];
__device__ __align__(16) float g_UB[NB * 8 * D];
__device__ __align__(16) float g_dise[NB * D];
__device__ int g_cnt[NB];

typedef unsigned long long ull;

__device__ __forceinline__ float leaky(float x) { return fmaxf(x, 0.2f * x); }
__device__ __forceinline__ float avgw(int cnt)  { return cnt > 0 ? 1.0f / ((float)cnt + 1e-8f) : 0.0f; }

__device__ __forceinline__ ull pack2(float x, float y) {
    ull r; asm("mov.b64 %0, {%1, %2};" : "=l"(r) : "f"(x), "f"(y)); return r;
}
__device__ __forceinline__ float2 unpack2(ull v) {
    float2 f; asm("mov.b64 {%0, %1}, %2;" : "=f"(f.x), "=f"(f.y) : "l"(v)); return f;
}
__device__ __forceinline__ void fma2(ull& acc, ull a, ull b) {
    asm("fma.rn.f32x2 %0, %1, %2, %3;" : "=l"(acc) : "l"(a), "l"(b), "l"(acc));
}

__device__ __forceinline__ float4 ldh4(const __half* p) {
    uint2 raw = *(const uint2*)p;
    __half2 h0 = *reinterpret_cast<__half2*>(&raw.x);
    __half2 h1 = *reinterpret_cast<__half2*>(&raw.y);
    float2 a = __half22float2(h0), b = __half22float2(h1);
    return make_float4(a.x, a.y, b.x, b.y);
}

__device__ __forceinline__ ull ldw2(const __half* p) {
    __half2 h = *(const __half2*)p;
    float2 f = __half22float2(h);
    return pack2(f.x, f.y);
}

__device__ __forceinline__ unsigned h2bits(__half2 h) {
    return *reinterpret_cast<unsigned*>(&h);
}
__device__ __forceinline__ unsigned f2h2(float a, float b) {
    return h2bits(__floats2half2_rn(a, b));
}

// ---------------------------------------------------------------------------
// K0: prep — fp16 tables, scalar weight transpose, MMA fragments, counters
// ---------------------------------------------------------------------------
#define CV_S ((NS_ROWS * D / 4 + 255) / 256)   // 3126
#define CV_D ((ND_ROWS * D / 4 + 255) / 256)   // 126
#define TP_B 64
#define FR_B 10
#define CN_B 4
#define PREP_GRID (CV_S + CV_D + TP_B + FR_B + CN_B)

__global__ void __launch_bounds__(256)
k_prep(const float* __restrict__ E_s, const float* __restrict__ E_d,
       const float* __restrict__ w0, const float* __restrict__ w1,
       const float* __restrict__ w2, const float* __restrict__ w3,
       const float* __restrict__ w4, const float* __restrict__ w5,
       const float* __restrict__ w6, const float* __restrict__ w7) {
    int bid = blockIdx.x, t = threadIdx.x;
    if (bid < CV_S) {
        int i = bid * 256 + t;
        if (i < NS_ROWS * D / 4) {
            float4 v = *(const float4*)(E_s + i * 4);
            uint2 u; u.x = f2h2(v.x, v.y); u.y = f2h2(v.z, v.w);
            *(uint2*)(g_Es2 + i * 4) = u;
        }
    } else if (bid < CV_S + CV_D) {
        int i = (bid - CV_S) * 256 + t;
        if (i < ND_ROWS * D / 4) {
            float4 v = *(const float4*)(E_d + i * 4);
            uint2 u; u.x = f2h2(v.x, v.y); u.y = f2h2(v.z, v.w);
            *(uint2*)(g_Ed2 + i * 4) = u;
        }
    } else if (bid < CV_S + CV_D + TP_B) {
        const float* Ws[8] = {w0, w1, w2, w3, w4, w5, w6, w7};
        int k = (bid - CV_S - CV_D) * 256 + t;
#pragma unroll
        for (int p = 0; p < 2; ++p) {
            int idx = k + p * 16384;
            int m = idx >> 12, de = idx & 4095;
            int d = de >> 6, e = de & 63;
            g_Wt2[m * D * D + e * D + d] = __float2half_rn(Ws[m][d * D + e]);
        }
    } else if (bid < CV_S + CV_D + TP_B + FR_B) {
        int fidx = (bid - CV_S - CV_D - TP_B) * 256 + t;   // 0..2559
        if (fidx < 512) {
            // W3 A-fragments (mma.m16n8k16.row.col)
            int mc = fidx >> 7, kc = (fidx >> 5) & 3, lane = fidx & 31;
            int d = mc * 16 + (lane >> 2);
            int e = kc * 16 + (lane & 3) * 2;
            const float* W = w4;
            uint4 o;
            o.x = f2h2(W[d * D + e],           W[d * D + e + 1]);
            o.y = f2h2(W[(d + 8) * D + e],     W[(d + 8) * D + e + 1]);
            o.z = f2h2(W[d * D + e + 8],       W[d * D + e + 9]);
            o.w = f2h2(W[(d + 8) * D + e + 8], W[(d + 8) * D + e + 9]);
            *(uint4*)&g_W3f[fidx * 4] = o;
        } else if (fidx < 2560) {
            // concatenated dual-matvec fragments: pair 0 = (W_dsd_21|W_dsd_22),
            // pair 1 = (W_usu_21|W_usu_22); K=128 (kc 0..7)
            int idx2 = fidx - 512;             // 0..2047
            int pair = idx2 >> 10;
            int rem = idx2 & 1023;
            int mc = rem >> 8, kc = (rem >> 5) & 7, lane = rem & 31;
            const float* W = (kc < 4) ? (pair ? w5 : w0) : (pair ? w6 : w1);
            int e = (kc & 3) * 16 + (lane & 3) * 2;
            int d = mc * 16 + (lane >> 2);
            uint4 o;
            o.x = f2h2(W[d * D + e],           W[d * D + e + 1]);
            o.y = f2h2(W[(d + 8) * D + e],     W[(d + 8) * D + e + 1]);
            o.z = f2h2(W[d * D + e + 8],       W[d * D + e + 9]);
            o.w = f2h2(W[(d + 8) * D + e + 8], W[(d + 8) * D + e + 9]);
            *(uint4*)&g_Wcatf[idx2 * 4] = o;
        }
    } else {
        int i = (bid - CV_S - CV_D - TP_B - FR_B) * 256 + t;
        g_cnt[i] = 0;
    }
}

// HMMA dual-matvec helper: C[64][8] = A_frag @ B(shXh rows of 128 halves),
// leaky per element, column-sum into sL2[64]. nkc = number of k16 chunks.
template <int NKC>
__device__ __forceinline__ void hmma_colsum(const unsigned* frag, unsigned baddr,
                                            int c4, int l31, float* sL2) {
    float c0 = 0.f, c1 = 0.f, c2 = 0.f, c3 = 0.f;
#pragma unroll
    for (int kc = 0; kc < NKC; ++kc) {
        uint4 A = *(const uint4*)&frag[((c4 * NKC + kc) * 32 + l31) * 4];
        unsigned b0, b1;
        asm volatile("ldmatrix.sync.aligned.m8n8.x2.shared.b16 {%0,%1}, [%2];"
                     : "=r"(b0), "=r"(b1) : "r"(baddr + kc * 32));
        asm volatile("mma.sync.aligned.m16n8k16.row.col.f32.f16.f16.f32 "
                     "{%0,%1,%2,%3}, {%4,%5,%6,%7}, {%8,%9}, {%0,%1,%2,%3};"
                     : "+f"(c0), "+f"(c1), "+f"(c2), "+f"(c3)
                     : "r"(A.x), "r"(A.y), "r"(A.z), "r"(A.w), "r"(b0), "r"(b1));
    }
    float v01 = leaky(c0) + leaky(c1);
    float v23 = leaky(c2) + leaky(c3);
    v01 += __shfl_down_sync(0xffffffffu, v01, 2);
    v23 += __shfl_down_sync(0xffffffffu, v23, 2);
    v01 += __shfl_down_sync(0xffffffffu, v01, 1);
    v23 += __shfl_down_sync(0xffffffffu, v23, 1);
    if ((l31 & 3) == 0) {
        int dbase = c4 * 16 + (l31 >> 2);
        sL2[dbase] = v01;
        sL2[dbase + 8] = v23;
    }
}

// ---------------------------------------------------------------------------
// K1: blocks [0, NB): dsd per b.  blocks [NB, 9*NB): usu inner per (b,g).
// All big matvecs on tensor cores; 1-row tails scalar. 9th finisher finalizes.
// ---------------------------------------------------------------------------
__global__ void __launch_bounds__(128, 8)
k_inner(const int* __restrict__ label,
        const int* __restrict__ dsd_1, const int* __restrict__ dsd_2,
        const int* __restrict__ usu_1, const int* __restrict__ usu_2,
        const int* __restrict__ usu_3, float* __restrict__ out) {
    int t = threadIdx.x;
    int g16 = t >> 4, lane16 = t & 15, d4 = lane16 * 4;
    int c4 = t >> 5, d2 = (t & 31) * 2;
    int l31 = t & 31;

    __shared__ __align__(16) __half shXh[8 * XH2];   // HMMA B tile (rows of 128 halves)
    __shared__ float sL2[64];
    __shared__ __align__(16) float shX[XS];
    __shared__ __align__(16) float shY[XS];
    __shared__ float shP[4][D];
    __shared__ int sFin;

    unsigned baddr = (unsigned)__cvta_generic_to_shared(shXh)
                   + (unsigned)(((l31 & 7) * XH2 + ((l31 >> 3) & 1) * 8) * 2);

    int b;

    if (blockIdx.x >= NB) {
        // ===================== usu inner: one (b,g) per block ================
        int bg = blockIdx.x - NB;
        b = bg >> 3;

        float4 u = make_float4(0.f, 0.f, 0.f, 0.f);
        int c2m = 0;
        if (t < 16) {
            int iu = __ldg(usu_1 + bg);
            u = ldh4(g_Es2 + iu * D + t * 4);
            int4 m0 = __ldg((const int4*)(usu_2 + bg * 8));
            int4 m1 = __ldg((const int4*)(usu_2 + bg * 8 + 4));
            c2m = (m0.x != 0) + (m0.y != 0) + (m0.z != 0) + (m0.w != 0)
                + (m1.x != 0) + (m1.y != 0) + (m1.z != 0) + (m1.w != 0);
        }

        const int4* ip = (const int4*)(usu_3 + (bg * 8 + g16) * 16);
        int4 i0 = __ldg(ip), i1 = __ldg(ip + 1), i2 = __ldg(ip + 2), i3 = __ldg(ip + 3);
        int cnt = (i0.x != 0) + (i0.y != 0) + (i0.z != 0) + (i0.w != 0)
                + (i1.x != 0) + (i1.y != 0) + (i1.z != 0) + (i1.w != 0)
                + (i2.x != 0) + (i2.y != 0) + (i2.z != 0) + (i2.w != 0)
                + (i3.x != 0) + (i3.y != 0) + (i3.z != 0) + (i3.w != 0);

        float sx = 0.f, sy = 0.f, sz = 0.f, sw = 0.f;
#define ACC(ix) { float4 v = ldh4(g_Es2 + (ix) * D + d4); \
                  sx += v.x; sy += v.y; sz += v.z; sw += v.w; }
        ACC(i0.x) ACC(i0.y) ACC(i0.z) ACC(i0.w)
        ACC(i1.x) ACC(i1.y) ACC(i1.z) ACC(i1.w)
        ACC(i2.x) ACC(i2.y) ACC(i2.z) ACC(i2.w)
        ACC(i3.x) ACC(i3.y) ACC(i3.z) ACC(i3.w)
#undef ACC
        float w = avgw(cnt);
        {
            uint2 hh; hh.x = f2h2(sx * w, sy * w); hh.y = f2h2(sz * w, sw * w);
            *(uint2*)&shXh[g16 * XH2 + d4] = hh;
        }
        __syncthreads();

        hmma_colsum<4>(g_W3f, baddr, c4, l31, sL2);
        __syncthreads();

        if (t < 16) {
            int dd = t * 4;
            float4 S = *(float4*)&sL2[dd];
            float w2 = avgw(c2m);
            float Sx = S.x * w2, Sy = S.y * w2, Sz = S.z * w2, Sw = S.w * w2;
            *(float4*)&g_UA[bg * D + dd] = make_float4(u.x + Sx, u.y + Sy, u.z + Sz, u.w + Sw);
            *(float4*)&g_UB[bg * D + dd] = make_float4(Sx * u.x, Sy * u.y, Sz * u.z, Sw * u.w);
            __threadfence();
        }
        __syncthreads();
    } else {
        // ===================== dsd full path: one b per block ================
        b = blockIdx.x;

        float4 td4 = make_float4(0.f, 0.f, 0.f, 0.f);
        int c1 = 0;
        if (t < 16) {
            int lb = __ldg(label + b);
            td4 = ldh4(g_Ed2 + lb * D + t * 4);
            int4 m0 = __ldg((const int4*)(dsd_1 + b * 8));
            int4 m1 = __ldg((const int4*)(dsd_1 + b * 8 + 4));
            c1 = (m0.x != 0) + (m0.y != 0) + (m0.z != 0) + (m0.w != 0)
               + (m1.x != 0) + (m1.y != 0) + (m1.z != 0) + (m1.w != 0);
        }

        int ies = __ldg(dsd_1 + b * 8 + g16);
        const int4* ip = (const int4*)(dsd_2 + (b * 8 + g16) * 8);
        int4 i0 = __ldg(ip), i1 = __ldg(ip + 1);
        int cnt = (i0.x != 0) + (i0.y != 0) + (i0.z != 0) + (i0.w != 0)
                + (i1.x != 0) + (i1.y != 0) + (i1.z != 0) + (i1.w != 0);

        float4 es = ldh4(g_Es2 + ies * D + d4);
        float sx = 0.f, sy = 0.f, sz = 0.f, sw = 0.f;
#define ACC(ix) { float4 v = ldh4(g_Ed2 + (ix) * D + d4); \
                  sx += v.x; sy += v.y; sz += v.z; sw += v.w; }
        ACC(i0.x) ACC(i0.y) ACC(i0.z) ACC(i0.w)
        ACC(i1.x) ACC(i1.y) ACC(i1.z) ACC(i1.w)
#undef ACC
        float w = avgw(cnt);
        float ax = sx * w, ay = sy * w, az = sz * w, aw = sw * w;
        {
            uint2 hx; hx.x = f2h2(es.x + ax, es.y + ay); hx.y = f2h2(es.z + az, es.w + aw);
            uint2 hy; hy.x = f2h2(ax * es.x, ay * es.y); hy.y = f2h2(az * es.z, aw * es.w);
            *(uint2*)&shXh[g16 * XH2 + d4]      = hx;   // X part: cols [0,64)
            *(uint2*)&shXh[g16 * XH2 + 64 + d4] = hy;   // Y part: cols [64,128)
        }
        __syncthreads();

        // hop1 dual matvec via HMMA (K=128, pair 0 fragments)
        hmma_colsum<8>(g_Wcatf + 0, baddr, c4, l31, sL2);
        __syncthreads();

        // hop2 inputs
        if (t < 16) {
            int dd = t * 4;
            float4 A = *(float4*)&sL2[dd];
            float w1 = avgw(c1);
            float Ax = A.x * w1, Ay = A.y * w1, Az = A.z * w1, Aw = A.w * w1;
            *(float4*)&shX[dd] = make_float4(Ax + td4.x, Ay + td4.y, Az + td4.z, Aw + td4.w);
            *(float4*)&shY[dd] = make_float4(Ax * td4.x, Ay * td4.y, Az * td4.z, Aw * td4.w);
        }
        __syncthreads();

        // hop2 dual matvec W11/W12 (1 row, scalar)
        {
            const __half* W11t = g_Wt2 + 2 * D * D;
            const __half* W12t = g_Wt2 + 3 * D * D;
            ull acc = 0ull;
#pragma unroll
            for (int ep = 0; ep < 4; ++ep) {
                int e = c4 * 16 + ep * 4;
                float4 xv = *(const float4*)&shX[e];
                float4 yv = *(const float4*)&shY[e];
                fma2(acc, pack2(xv.x, xv.x), ldw2(W11t + (e + 0) * D + d2));
                fma2(acc, pack2(xv.y, xv.y), ldw2(W11t + (e + 1) * D + d2));
                fma2(acc, pack2(xv.z, xv.z), ldw2(W11t + (e + 2) * D + d2));
                fma2(acc, pack2(xv.w, xv.w), ldw2(W11t + (e + 3) * D + d2));
                fma2(acc, pack2(yv.x, yv.x), ldw2(W12t + (e + 0) * D + d2));
                fma2(acc, pack2(yv.y, yv.y), ldw2(W12t + (e + 1) * D + d2));
                fma2(acc, pack2(yv.z, yv.z), ldw2(W12t + (e + 2) * D + d2));
                fma2(acc, pack2(yv.w, yv.w), ldw2(W12t + (e + 3) * D + d2));
            }
            *(float2*)&shP[c4][d2] = unpack2(acc);
        }
        __syncthreads();

        if (t < 16) {
            int dd = t * 4;
            float rx = 0.f, ry = 0.f, rz = 0.f, rw = 0.f;
#pragma unroll
            for (int c = 0; c < 4; ++c) {
                float4 p = *(float4*)&shP[c][dd];
                rx += p.x; ry += p.y; rz += p.z; rw += p.w;
            }
            *(float4*)&g_dise[b * D + dd] =
                make_float4(leaky(rx), leaky(ry), leaky(rz), leaky(rw));
            __threadfence();
        }
        __syncthreads();
    }

    // ======================= completion + finalization =======================
    if (t == 0) {
        int old = atomicAdd(&g_cnt[b], 1);
        if (old == 8) { __threadfence(); sFin = 1; } else sFin = 0;
    }
    __syncthreads();
    if (!sFin) return;

    // --- finalization: es1 HMMA + i-avg + W1u matvec + dot with dise ---
    float4 dz = make_float4(0.f, 0.f, 0.f, 0.f);
    int c1u = 0;
    if (t < 16) {
        dz = *(const float4*)&g_dise[b * D + t * 4];
        int4 m0 = __ldg((const int4*)(usu_1 + b * 8));
        int4 m1 = __ldg((const int4*)(usu_1 + b * 8 + 4));
        c1u = (m0.x != 0) + (m0.y != 0) + (m0.z != 0) + (m0.w != 0)
            + (m1.x != 0) + (m1.y != 0) + (m1.z != 0) + (m1.w != 0);
    }
    {
        float4 a = *(const float4*)&g_UA[(b * 8 + g16) * D + d4];
        float4 y = *(const float4*)&g_UB[(b * 8 + g16) * D + d4];
        uint2 hx; hx.x = f2h2(a.x, a.y); hx.y = f2h2(a.z, a.w);
        uint2 hy; hy.x = f2h2(y.x, y.y); hy.y = f2h2(y.z, y.w);
        *(uint2*)&shXh[g16 * XH2 + d4]      = hx;
        *(uint2*)&shXh[g16 * XH2 + 64 + d4] = hy;
    }
    __syncthreads();

    // es1 dual matvec via HMMA (K=128, pair 1 fragments)
    hmma_colsum<8>(g_Wcatf + 4 * 8 * 32 * 4, baddr, c4, l31, sL2);
    __syncthreads();

    // i-avg
    if (t < 16) {
        int dd = t * 4;
        float4 Tv = *(float4*)&sL2[dd];
        float w1 = avgw(c1u);
        *(float4*)&shX[dd] = make_float4(Tv.x * w1, Tv.y * w1, Tv.z * w1, Tv.w * w1);
    }
    __syncthreads();

    // emb_user matvec W1u (1 row, scalar)
    {
        const __half* W1t = g_Wt2 + 7 * D * D;
        ull acc = 0ull;
#pragma unroll
        for (int ep = 0; ep < 4; ++ep) {
            int e = c4 * 16 + ep * 4;
            float4 xv = *(const float4*)&shX[e];
            fma2(acc, pack2(xv.x, xv.x), ldw2(W1t + (e + 0) * D + d2));
            fma2(acc, pack2(xv.y, xv.y), ldw2(W1t + (e + 1) * D + d2));
            fma2(acc, pack2(xv.z, xv.z), ldw2(W1t + (e + 2) * D + d2));
            fma2(acc, pack2(xv.w, xv.w), ldw2(W1t + (e + 3) * D + d2));
        }
        *(float2*)&shP[c4][d2] = unpack2(acc);
    }
    __syncthreads();

    // final reduce + dot with emb_dise
    if (t < 16) {
        int dd = t * 4;
        float rx = 0.f, ry = 0.f, rz = 0.f, rw = 0.f;
#pragma unroll
        for (int c = 0; c < 4; ++c) {
            float4 p = *(float4*)&shP[c][dd];
            rx += p.x; ry += p.y; rz += p.z; rw += p.w;
        }
        float v = leaky(rx) * dz.x + leaky(ry) * dz.y +
                  leaky(rz) * dz.z + leaky(rw) * dz.w;
        v += __shfl_down_sync(0x0000ffffu, v, 8, 16);
        v += __shfl_down_sync(0x0000ffffu, v, 4, 16);
        v += __shfl_down_sync(0x0000ffffu, v, 2, 16);
        v += __shfl_down_sync(0x0000ffffu, v, 1, 16);
        if (t == 0) out[b] = v;
    }
}

// ---------------------------------------------------------------------------
extern "C" void kernel_launch(void* const* d_in, const int* in_sizes, int n_in,
                              void* d_out, int out_size) {
    const float* E_s = (const float*)d_in[0];
    const float* E_d = (const float*)d_in[1];
    // weights: W_dsd_21, W_dsd_22, W_dsd_11, W_dsd_12, W_usu_3, W_usu_21, W_usu_22, W_usu_1
    k_prep<<<PREP_GRID, 256>>>(E_s, E_d,
                               (const float*)d_in[2], (const float*)d_in[3],
                               (const float*)d_in[4], (const float*)d_in[5],
                               (const float*)d_in[6], (const float*)d_in[7],
                               (const float*)d_in[8], (const float*)d_in[9]);

    k_inner<<<NB * 9, 128>>>((const int*)d_in[10], (const int*)d_in[11],
                             (const int*)d_in[12], (const int*)d_in[13],
                             (const int*)d_in[14], (const int*)d_in[15],
                             (float*)d_out);
}

// round 17
// speedup vs baseline: 1.4739x; 1.0590x over previous
#include <cuda_runtime.h>
#include <cuda_fp16.h>

#define D 64
#define NB 1024
#define XS 68
#define XH2 136   // half smem row stride for HMMA tiles (272B, conflict-free)

#define NS_ROWS 50001
#define ND_ROWS 2001

// Scratch (allocation-free rule: __device__ globals)
__device__ __align__(16) __half g_Wt2[8 * D * D];        // fp16 Wt (scalar paths)
__device__ __align__(16) unsigned g_W3f[4 * 4 * 32 * 4]; // W3 A-fragments
__device__ __align__(16) unsigned g_Wcatf[2 * 4 * 8 * 32 * 4]; // [pair][mc][kc][lane][4]
__device__ __align__(16) __half g_Es2[NS_ROWS * D];
__device__ __align__(16) __half g_Ed2[ND_ROWS * D];
__device__ __align__(16) float g_UA[NB * 8 * D];
__device__ __align__(16) float g_UB[NB * 8 * D];
__device__ __align__(16) float g_dise[NB * D];
__device__ int g_cnt[NB];

typedef unsigned long long ull;

__device__ __forceinline__ float leaky(float x) { return fmaxf(x, 0.2f * x); }
__device__ __forceinline__ float avgw(int cnt)  { return cnt > 0 ? 1.0f / ((float)cnt + 1e-8f) : 0.0f; }

__device__ __forceinline__ ull pack2(float x, float y) {
    ull r; asm("mov.b64 %0, {%1, %2};" : "=l"(r) : "f"(x), "f"(y)); return r;
}
__device__ __forceinline__ float2 unpack2(ull v) {
    float2 f; asm("mov.b64 {%0, %1}, %2;" : "=f"(f.x), "=f"(f.y) : "l"(v)); return f;
}
__device__ __forceinline__ void fma2(ull& acc, ull a, ull b) {
    asm("fma.rn.f32x2 %0, %1, %2, %3;" : "=l"(acc) : "l"(a), "l"(b), "l"(acc));
}

__device__ __forceinline__ float4 ldh4(const __half* p) {
    uint2 raw = *(const uint2*)p;
    __half2 h0 = *reinterpret_cast<__half2*>(&raw.x);
    __half2 h1 = *reinterpret_cast<__half2*>(&raw.y);
    float2 a = __half22float2(h0), b = __half22float2(h1);
    return make_float4(a.x, a.y, b.x, b.y);
}

__device__ __forceinline__ ull ldw2(const __half* p) {
    __half2 h = *(const __half2*)p;
    float2 f = __half22float2(h);
    return pack2(f.x, f.y);
}

__device__ __forceinline__ unsigned h2bits(__half2 h) {
    return *reinterpret_cast<unsigned*>(&h);
}
__device__ __forceinline__ unsigned f2h2(float a, float b) {
    return h2bits(__floats2half2_rn(a, b));
}

// ---------------------------------------------------------------------------
// K0: prep — fp16 tables, scalar weight transpose, MMA fragments, counters
// ---------------------------------------------------------------------------
#define CV_S ((NS_ROWS * D / 4 + 255) / 256)   // 3126
#define CV_D ((ND_ROWS * D / 4 + 255) / 256)   // 126
#define TP_B 64
#define FR_B 10
#define CN_B 4
#define PREP_GRID (CV_S + CV_D + TP_B + FR_B + CN_B)

__global__ void __launch_bounds__(256)
k_prep(const float* __restrict__ E_s, const float* __restrict__ E_d,
       const float* __restrict__ w0, const float* __restrict__ w1,
       const float* __restrict__ w2, const float* __restrict__ w3,
       const float* __restrict__ w4, const float* __restrict__ w5,
       const float* __restrict__ w6, const float* __restrict__ w7) {
    int bid = blockIdx.x, t = threadIdx.x;
    if (bid < CV_S) {
        int i = bid * 256 + t;
        if (i < NS_ROWS * D / 4) {
            float4 v = *(const float4*)(E_s + i * 4);
            uint2 u; u.x = f2h2(v.x, v.y); u.y = f2h2(v.z, v.w);
            *(uint2*)(g_Es2 + i * 4) = u;
        }
    } else if (bid < CV_S + CV_D) {
        int i = (bid - CV_S) * 256 + t;
        if (i < ND_ROWS * D / 4) {
            float4 v = *(const float4*)(E_d + i * 4);
            uint2 u; u.x = f2h2(v.x, v.y); u.y = f2h2(v.z, v.w);
            *(uint2*)(g_Ed2 + i * 4) = u;
        }
    } else if (bid < CV_S + CV_D + TP_B) {
        const float* Ws[8] = {w0, w1, w2, w3, w4, w5, w6, w7};
        int k = (bid - CV_S - CV_D) * 256 + t;
#pragma unroll
        for (int p = 0; p < 2; ++p) {
            int idx = k + p * 16384;
            int m = idx >> 12, de = idx & 4095;
            int d = de >> 6, e = de & 63;
            g_Wt2[m * D * D + e * D + d] = __float2half_rn(Ws[m][d * D + e]);
        }
    } else if (bid < CV_S + CV_D + TP_B + FR_B) {
        int fidx = (bid - CV_S - CV_D - TP_B) * 256 + t;   // 0..2559
        if (fidx < 512) {
            int mc = fidx >> 7, kc = (fidx >> 5) & 3, lane = fidx & 31;
            int d = mc * 16 + (lane >> 2);
            int e = kc * 16 + (lane & 3) * 2;
            const float* W = w4;
            uint4 o;
            o.x = f2h2(W[d * D + e],           W[d * D + e + 1]);
            o.y = f2h2(W[(d + 8) * D + e],     W[(d + 8) * D + e + 1]);
            o.z = f2h2(W[d * D + e + 8],       W[d * D + e + 9]);
            o.w = f2h2(W[(d + 8) * D + e + 8], W[(d + 8) * D + e + 9]);
            *(uint4*)&g_W3f[fidx * 4] = o;
        } else if (fidx < 2560) {
            int idx2 = fidx - 512;
            int pair = idx2 >> 10;
            int rem = idx2 & 1023;
            int mc = rem >> 8, kc = (rem >> 5) & 7, lane = rem & 31;
            const float* W = (kc < 4) ? (pair ? w5 : w0) : (pair ? w6 : w1);
            int e = (kc & 3) * 16 + (lane & 3) * 2;
            int d = mc * 16 + (lane >> 2);
            uint4 o;
            o.x = f2h2(W[d * D + e],           W[d * D + e + 1]);
            o.y = f2h2(W[(d + 8) * D + e],     W[(d + 8) * D + e + 1]);
            o.z = f2h2(W[d * D + e + 8],       W[d * D + e + 9]);
            o.w = f2h2(W[(d + 8) * D + e + 8], W[(d + 8) * D + e + 9]);
            *(uint4*)&g_Wcatf[idx2 * 4] = o;
        }
    } else {
        int i = (bid - CV_S - CV_D - TP_B - FR_B) * 256 + t;
        g_cnt[i] = 0;
    }
}

// HMMA helper with ldmatrix.x4 (2 k-chunks per load). NKC must be even.
template <int NKC>
__device__ __forceinline__ void hmma_colsum(const unsigned* frag, unsigned baddr4,
                                            int c4, int l31, float* sL2) {
    float c0 = 0.f, c1 = 0.f, c2 = 0.f, c3 = 0.f;
#pragma unroll
    for (int kc2 = 0; kc2 < NKC / 2; ++kc2) {
        uint4 A0 = *(const uint4*)&frag[((c4 * NKC + 2 * kc2) * 32 + l31) * 4];
        uint4 A1 = *(const uint4*)&frag[((c4 * NKC + 2 * kc2 + 1) * 32 + l31) * 4];
        unsigned b0, b1, b2, b3;
        asm volatile("ldmatrix.sync.aligned.m8n8.x4.shared.b16 {%0,%1,%2,%3}, [%4];"
                     : "=r"(b0), "=r"(b1), "=r"(b2), "=r"(b3)
                     : "r"(baddr4 + kc2 * 64));
        asm volatile("mma.sync.aligned.m16n8k16.row.col.f32.f16.f16.f32 "
                     "{%0,%1,%2,%3}, {%4,%5,%6,%7}, {%8,%9}, {%0,%1,%2,%3};"
                     : "+f"(c0), "+f"(c1), "+f"(c2), "+f"(c3)
                     : "r"(A0.x), "r"(A0.y), "r"(A0.z), "r"(A0.w), "r"(b0), "r"(b1));
        asm volatile("mma.sync.aligned.m16n8k16.row.col.f32.f16.f16.f32 "
                     "{%0,%1,%2,%3}, {%4,%5,%6,%7}, {%8,%9}, {%0,%1,%2,%3};"
                     : "+f"(c0), "+f"(c1), "+f"(c2), "+f"(c3)
                     : "r"(A1.x), "r"(A1.y), "r"(A1.z), "r"(A1.w), "r"(b2), "r"(b3));
    }
    float v01 = leaky(c0) + leaky(c1);
    float v23 = leaky(c2) + leaky(c3);
    v01 += __shfl_down_sync(0xffffffffu, v01, 2);
    v23 += __shfl_down_sync(0xffffffffu, v23, 2);
    v01 += __shfl_down_sync(0xffffffffu, v01, 1);
    v23 += __shfl_down_sync(0xffffffffu, v23, 1);
    if ((l31 & 3) == 0) {
        int dbase = c4 * 16 + (l31 >> 2);
        sL2[dbase] = v01;
        sL2[dbase + 8] = v23;
    }
}

// ---------------------------------------------------------------------------
// K1: blocks [0, NB): dsd per b.  blocks [NB, 9*NB): usu inner per (b,g).
// ---------------------------------------------------------------------------
__global__ void __launch_bounds__(128, 8)
k_inner(const int* __restrict__ label,
        const int* __restrict__ dsd_1, const int* __restrict__ dsd_2,
        const int* __restrict__ usu_1, const int* __restrict__ usu_2,
        const int* __restrict__ usu_3, float* __restrict__ out) {
    int t = threadIdx.x;
    int g16 = t >> 4, lane16 = t & 15, d4 = lane16 * 4;
    int c4 = t >> 5, d2 = (t & 31) * 2;
    int l31 = t & 31;

    __shared__ __align__(16) __half shXh[8 * XH2];
    __shared__ float sL2[64];
    __shared__ __align__(16) float shX[XS];
    __shared__ __align__(16) float shY[XS];
    __shared__ float shP[4][D];
    __shared__ int sFin;

    // ldmatrix.x4 address: lanes 0-15 -> k-chunk even (e, e+8), 16-31 -> odd
    unsigned baddr4 = (unsigned)__cvta_generic_to_shared(shXh)
                    + (unsigned)(((l31 & 7) * XH2 + (l31 >> 3) * 8) * 2);

    int b;

    if (blockIdx.x >= NB) {
        // ===================== usu inner: one (b,g) per block ================
        int bg = blockIdx.x - NB;
        b = bg >> 3;

        float4 u = make_float4(0.f, 0.f, 0.f, 0.f);
        int c2m = 0;
        if (t < 16) {
            int iu = __ldg(usu_1 + bg);
            u = ldh4(g_Es2 + iu * D + t * 4);
            int4 m0 = __ldg((const int4*)(usu_2 + bg * 8));
            int4 m1 = __ldg((const int4*)(usu_2 + bg * 8 + 4));
            c2m = (m0.x != 0) + (m0.y != 0) + (m0.z != 0) + (m0.w != 0)
                + (m1.x != 0) + (m1.y != 0) + (m1.z != 0) + (m1.w != 0);
        }

        const int4* ip = (const int4*)(usu_3 + (bg * 8 + g16) * 16);
        int4 i0 = __ldg(ip), i1 = __ldg(ip + 1), i2 = __ldg(ip + 2), i3 = __ldg(ip + 3);
        int cnt = (i0.x != 0) + (i0.y != 0) + (i0.z != 0) + (i0.w != 0)
                + (i1.x != 0) + (i1.y != 0) + (i1.z != 0) + (i1.w != 0)
                + (i2.x != 0) + (i2.y != 0) + (i2.z != 0) + (i2.w != 0)
                + (i3.x != 0) + (i3.y != 0) + (i3.z != 0) + (i3.w != 0);

        float sx = 0.f, sy = 0.f, sz = 0.f, sw = 0.f;
        // pairwise fp16 add, then widen (halves cvt count)
#define ACC2(ia, ib) { \
        uint2 ra = *(const uint2*)(g_Es2 + (ia) * D + d4); \
        uint2 rb = *(const uint2*)(g_Es2 + (ib) * D + d4); \
        __half2 s0 = __hadd2(*(__half2*)&ra.x, *(__half2*)&rb.x); \
        __half2 s1 = __hadd2(*(__half2*)&ra.y, *(__half2*)&rb.y); \
        float2 f0 = __half22float2(s0), f1 = __half22float2(s1); \
        sx += f0.x; sy += f0.y; sz += f1.x; sw += f1.y; }
        ACC2(i0.x, i0.y) ACC2(i0.z, i0.w)
        ACC2(i1.x, i1.y) ACC2(i1.z, i1.w)
        ACC2(i2.x, i2.y) ACC2(i2.z, i2.w)
        ACC2(i3.x, i3.y) ACC2(i3.z, i3.w)
#undef ACC2
        float w = avgw(cnt);
        {
            uint2 hh; hh.x = f2h2(sx * w, sy * w); hh.y = f2h2(sz * w, sw * w);
            *(uint2*)&shXh[g16 * XH2 + d4] = hh;
        }
        __syncthreads();

        hmma_colsum<4>(g_W3f, baddr4, c4, l31, sL2);
        __syncthreads();

        if (t < 16) {
            int dd = t * 4;
            float4 S = *(float4*)&sL2[dd];
            float w2 = avgw(c2m);
            float Sx = S.x * w2, Sy = S.y * w2, Sz = S.z * w2, Sw = S.w * w2;
            *(float4*)&g_UA[bg * D + dd] = make_float4(u.x + Sx, u.y + Sy, u.z + Sz, u.w + Sw);
            *(float4*)&g_UB[bg * D + dd] = make_float4(Sx * u.x, Sy * u.y, Sz * u.z, Sw * u.w);
            __threadfence();
        }
        __syncthreads();
    } else {
        // ===================== dsd full path: one b per block ================
        b = blockIdx.x;

        float4 td4 = make_float4(0.f, 0.f, 0.f, 0.f);
        int c1 = 0;
        if (t < 16) {
            int lb = __ldg(label + b);
            td4 = ldh4(g_Ed2 + lb * D + t * 4);
            int4 m0 = __ldg((const int4*)(dsd_1 + b * 8));
            int4 m1 = __ldg((const int4*)(dsd_1 + b * 8 + 4));
            c1 = (m0.x != 0) + (m0.y != 0) + (m0.z != 0) + (m0.w != 0)
               + (m1.x != 0) + (m1.y != 0) + (m1.z != 0) + (m1.w != 0);
        }

        int ies = __ldg(dsd_1 + b * 8 + g16);
        const int4* ip = (const int4*)(dsd_2 + (b * 8 + g16) * 8);
        int4 i0 = __ldg(ip), i1 = __ldg(ip + 1);
        int cnt = (i0.x != 0) + (i0.y != 0) + (i0.z != 0) + (i0.w != 0)
                + (i1.x != 0) + (i1.y != 0) + (i1.z != 0) + (i1.w != 0);

        float4 es = ldh4(g_Es2 + ies * D + d4);
        float sx = 0.f, sy = 0.f, sz = 0.f, sw = 0.f;
#define ACC2(ia, ib) { \
        uint2 ra = *(const uint2*)(g_Ed2 + (ia) * D + d4); \
        uint2 rb = *(const uint2*)(g_Ed2 + (ib) * D + d4); \
        __half2 s0 = __hadd2(*(__half2*)&ra.x, *(__half2*)&rb.x); \
        __half2 s1 = __hadd2(*(__half2*)&ra.y, *(__half2*)&rb.y); \
        float2 f0 = __half22float2(s0), f1 = __half22float2(s1); \
        sx += f0.x; sy += f0.y; sz += f1.x; sw += f1.y; }
        ACC2(i0.x, i0.y) ACC2(i0.z, i0.w)
        ACC2(i1.x, i1.y) ACC2(i1.z, i1.w)
#undef ACC2
        float w = avgw(cnt);
        float ax = sx * w, ay = sy * w, az = sz * w, aw = sw * w;
        {
            uint2 hx; hx.x = f2h2(es.x + ax, es.y + ay); hx.y = f2h2(es.z + az, es.w + aw);
            uint2 hy; hy.x = f2h2(ax * es.x, ay * es.y); hy.y = f2h2(az * es.z, aw * es.w);
            *(uint2*)&shXh[g16 * XH2 + d4]      = hx;
            *(uint2*)&shXh[g16 * XH2 + 64 + d4] = hy;
        }
        __syncthreads();

        hmma_colsum<8>(g_Wcatf + 0, baddr4, c4, l31, sL2);
        __syncthreads();

        if (t < 16) {
            int dd = t * 4;
            float4 A = *(float4*)&sL2[dd];
            float w1 = avgw(c1);
            float Ax = A.x * w1, Ay = A.y * w1, Az = A.z * w1, Aw = A.w * w1;
            *(float4*)&shX[dd] = make_float4(Ax + td4.x, Ay + td4.y, Az + td4.z, Aw + td4.w);
            *(float4*)&shY[dd] = make_float4(Ax * td4.x, Ay * td4.y, Az * td4.z, Aw * td4.w);
        }
        __syncthreads();

        // hop2 dual matvec W11/W12 (1 row, scalar)
        {
            const __half* W11t = g_Wt2 + 2 * D * D;
            const __half* W12t = g_Wt2 + 3 * D * D;
            ull acc = 0ull;
#pragma unroll
            for (int ep = 0; ep < 4; ++ep) {
                int e = c4 * 16 + ep * 4;
                float4 xv = *(const float4*)&shX[e];
                float4 yv = *(const float4*)&shY[e];
                fma2(acc, pack2(xv.x, xv.x), ldw2(W11t + (e + 0) * D + d2));
                fma2(acc, pack2(xv.y, xv.y), ldw2(W11t + (e + 1) * D + d2));
                fma2(acc, pack2(xv.z, xv.z), ldw2(W11t + (e + 2) * D + d2));
                fma2(acc, pack2(xv.w, xv.w), ldw2(W11t + (e + 3) * D + d2));
                fma2(acc, pack2(yv.x, yv.x), ldw2(W12t + (e + 0) * D + d2));
                fma2(acc, pack2(yv.y, yv.y), ldw2(W12t + (e + 1) * D + d2));
                fma2(acc, pack2(yv.z, yv.z), ldw2(W12t + (e + 2) * D + d2));
                fma2(acc, pack2(yv.w, yv.w), ldw2(W12t + (e + 3) * D + d2));
            }
            *(float2*)&shP[c4][d2] = unpack2(acc);
        }
        __syncthreads();

        if (t < 16) {
            int dd = t * 4;
            float rx = 0.f, ry = 0.f, rz = 0.f, rw = 0.f;
#pragma unroll
            for (int c = 0; c < 4; ++c) {
                float4 p = *(float4*)&shP[c][dd];
                rx += p.x; ry += p.y; rz += p.z; rw += p.w;
            }
            *(float4*)&g_dise[b * D + dd] =
                make_float4(leaky(rx), leaky(ry), leaky(rz), leaky(rw));
            __threadfence();
        }
        __syncthreads();
    }

    // ======================= completion + finalization =======================
    if (t == 0) {
        int old = atomicAdd(&g_cnt[b], 1);
        if (old == 8) { __threadfence(); sFin = 1; } else sFin = 0;
    }
    __syncthreads();
    if (!sFin) return;

    // --- finalization: es1 HMMA + i-avg + W1u matvec + dot with dise ---
    float4 dz = make_float4(0.f, 0.f, 0.f, 0.f);
    int c1u = 0;
    if (t < 16) {
        dz = *(const float4*)&g_dise[b * D + t * 4];
        int4 m0 = __ldg((const int4*)(usu_1 + b * 8));
        int4 m1 = __ldg((const int4*)(usu_1 + b * 8 + 4));
        c1u = (m0.x != 0) + (m0.y != 0) + (m0.z != 0) + (m0.w != 0)
            + (m1.x != 0) + (m1.y != 0) + (m1.z != 0) + (m1.w != 0);
    }
    {
        float4 a = *(const float4*)&g_UA[(b * 8 + g16) * D + d4];
        float4 y = *(const float4*)&g_UB[(b * 8 + g16) * D + d4];
        uint2 hx; hx.x = f2h2(a.x, a.y); hx.y = f2h2(a.z, a.w);
        uint2 hy; hy.x = f2h2(y.x, y.y); hy.y = f2h2(y.z, y.w);
        *(uint2*)&shXh[g16 * XH2 + d4]      = hx;
        *(uint2*)&shXh[g16 * XH2 + 64 + d4] = hy;
    }
    __syncthreads();

    hmma_colsum<8>(g_Wcatf + 4 * 8 * 32 * 4, baddr4, c4, l31, sL2);
    __syncthreads();

    if (t < 16) {
        int dd = t * 4;
        float4 Tv = *(float4*)&sL2[dd];
        float w1 = avgw(c1u);
        *(float4*)&shX[dd] = make_float4(Tv.x * w1, Tv.y * w1, Tv.z * w1, Tv.w * w1);
    }
    __syncthreads();

    // emb_user matvec W1u (1 row, scalar)
    {
        const __half* W1t = g_Wt2 + 7 * D * D;
        ull acc = 0ull;
#pragma unroll
        for (int ep = 0; ep < 4; ++ep) {
            int e = c4 * 16 + ep * 4;
            float4 xv = *(const float4*)&shX[e];
            fma2(acc, pack2(xv.x, xv.x), ldw2(W1t + (e + 0) * D + d2));
            fma2(acc, pack2(xv.y, xv.y), ldw2(W1t + (e + 1) * D + d2));
            fma2(acc, pack2(xv.z, xv.z), ldw2(W1t + (e + 2) * D + d2));
            fma2(acc, pack2(xv.w, xv.w), ldw2(W1t + (e + 3) * D + d2));
        }
        *(float2*)&shP[c4][d2] = unpack2(acc);
    }
    __syncthreads();

    // final reduce + dot with emb_dise
    if (t < 16) {
        int dd = t * 4;
        float rx = 0.f, ry = 0.f, rz = 0.f, rw = 0.f;
#pragma unroll
        for (int c = 0; c < 4; ++c) {
            float4 p = *(float4*)&shP[c][dd];
            rx += p.x; ry += p.y; rz += p.z; rw += p.w;
        }
        float v = leaky(rx) * dz.x + leaky(ry) * dz.y +
                  leaky(rz) * dz.z + leaky(rw) * dz.w;
        v += __shfl_down_sync(0x0000ffffu, v, 8, 16);
        v += __shfl_down_sync(0x0000ffffu, v, 4, 16);
        v += __shfl_down_sync(0x0000ffffu, v, 2, 16);
        v += __shfl_down_sync(0x0000ffffu, v, 1, 16);
        if (t == 0) out[b] = v;
    }
}

// ---------------------------------------------------------------------------
extern "C" void kernel_launch(void* const* d_in, const int* in_sizes, int n_in,
                              void* d_out, int out_size) {
    const float* E_s = (const float*)d_in[0];
    const float* E_d = (const float*)d_in[1];
    // weights: W_dsd_21, W_dsd_22, W_dsd_11, W_dsd_12, W_usu_3, W_usu_21, W_usu_22, W_usu_1
    k_prep<<<PREP_GRID, 256>>>(E_s, E_d,
                               (const float*)d_in[2], (const float*)d_in[3],
                               (const float*)d_in[4], (const float*)d_in[5],
                               (const float*)d_in[6], (const float*)d_in[7],
                               (const float*)d_in[8], (const float*)d_in[9]);

    k_inner<<<NB * 9, 128>>>((const int*)d_in[10], (const int*)d_in[11],
                             (const int*)d_in[12], (const int*)d_in[13],
                             (const int*)d_in[14], (const int*)d_in[15],
                             (float*)d_out);
}